// round 14
// baseline (speedup 1.0000x reference)
#include <cuda_runtime.h>
#include <cuda_bf16.h>
#include <math.h>
#include <stdint.h>

// ---------------- problem constants ----------------
#define BATCH 4
#define DM    192
#define DI    384
#define DS    16
#define DR    12
#define NSEQ  1024
#define LROWS 4096
#define NDIR  4
#define DBL_W 44

typedef __nv_bfloat16 bf16;

// ---------------- scratch ----------------
__device__ float g_xs  [LROWS*DM];
__device__ float g_dbl [NDIR*LROWS*DBL_W];
__device__ float g_h3  [LROWS*DM];
__device__ float g_cb  [DM];

__device__ bf16 g_xs_h  [LROWS*DM];
__device__ bf16 g_xp_h  [LROWS*DM];
__device__ bf16 g_xz_h  [(long)NDIR*LROWS*2*DI];
__device__ bf16 g_xsm_h [NDIR*LROWS*DI];
__device__ bf16 g_y_h   [NDIR*LROWS*DI];
__device__ bf16 g_fused_h[LROWS*4*DM];
__device__ bf16 g_hdn_h [LROWS*2*DM];

__device__ bf16 g_w_in_h    [DM*DM];
__device__ bf16 g_w_inproj_h[NDIR*2*DI*DM];
__device__ bf16 g_w_xp_h    [NDIR*DBL_W*DI];
__device__ bf16 g_w_out_h   [NDIR*DM*DI];
__device__ bf16 g_w_f1_h    [2*DM*4*DM];
__device__ bf16 g_w_ow_h    [DM*DM];          // o_w bf16
__device__ bf16 g_w_f2T     [2*DM*DM];        // f_w2^T bf16
__device__ bf16 g_cw_h      [DM*2*DM];        // o_w @ f_w2 (bf16, via GEMM)

// ---------------- helpers ----------------
__device__ __forceinline__ float apply_act(float v, int act) {
    if (act == 1) {
        v = (v > 20.f) ? v : __logf(1.f + __expf(v));
    } else if (act == 2) {
        v = 0.5f * v * (1.f + erff(v * 0.70710678118654752f));
    }
    return v;
}

__device__ __forceinline__ int seq_src_n(int d, int t) {
    if (d == 0) return t;
    if (d == 1) return NSEQ - 1 - t;
    if (d == 2) return ((t & 31) << 5) + (t >> 5);
    int u = NSEQ - 1 - t;
    return ((u & 31) << 5) + (u >> 5);
}

__device__ __forceinline__ void mma_bf16(float4& c,
    uint32_t a0, uint32_t a1, uint32_t a2, uint32_t a3, uint32_t b0, uint32_t b1) {
    asm volatile(
        "mma.sync.aligned.m16n8k16.row.col.f32.bf16.bf16.f32 "
        "{%0,%1,%2,%3}, {%4,%5,%6,%7}, {%8,%9}, {%0,%1,%2,%3};\n"
        : "+f"(c.x), "+f"(c.y), "+f"(c.z), "+f"(c.w)
        : "r"(a0), "r"(a1), "r"(a2), "r"(a3), "r"(b0), "r"(b1));
}

__device__ __forceinline__ void ldsm_x4(uint32_t addr,
    uint32_t& r0, uint32_t& r1, uint32_t& r2, uint32_t& r3) {
    asm volatile("ldmatrix.sync.aligned.m8n8.x4.shared.b16 {%0,%1,%2,%3}, [%4];"
        : "=r"(r0), "=r"(r1), "=r"(r2), "=r"(r3) : "r"(addr));
}

__device__ __forceinline__ uint32_t pack_bf2(float lo, float hi) {
    __nv_bfloat162 p = __floats2bfloat162_rn(lo, hi);
    return *(uint32_t*)&p;
}

__device__ __forceinline__ void cp16(uint32_t saddr, const void* gptr, int src_bytes) {
    asm volatile("cp.async.cg.shared.global [%0], [%1], 16, %2;\n"
        :: "r"(saddr), "l"(gptr), "r"(src_bytes));
}
__device__ __forceinline__ void cp_commit() {
    asm volatile("cp.async.commit_group;\n");
}
__device__ __forceinline__ void cp_wait2() { asm volatile("cp.async.wait_group 2;\n"); }
__device__ __forceinline__ void cp_wait1() { asm volatile("cp.async.wait_group 1;\n"); }
__device__ __forceinline__ void cp_wait0() { asm volatile("cp.async.wait_group 0;\n"); }

// ---------------- prep: conversions + transposes + bias + ln1 (one launch) ----------------
#define N_WCONV (DM*DM + NDIR*2*DI*DM + NDIR*DBL_W*DI + NDIR*DM*DI + 2*DM*4*DM)
#define NWB ((N_WCONV + 255) / 256)
#define N_OW  (DM*DM)
#define N_F2T (2*DM*DM)
#define B_OW  ((N_OW + 255) / 256)
#define B_F2T ((N_F2T + 255) / 256)
#define NLN1 128

__global__ __launch_bounds__(256) void prep_w_kernel(
    const float* s0, const float* s1, const float* s2, const float* s3, const float* s4,
    const float* __restrict__ o_w, const float* __restrict__ o_b,
    const float* __restrict__ f_w2, const float* __restrict__ f_b2,
    const float* __restrict__ x, const float* __restrict__ ng, const float* __restrict__ nb)
{
    __shared__ float sh[DM * 33 + 64];
    const int tid = threadIdx.x;
    int blk = blockIdx.x;

    if (blk < NWB) {
        const int n0 = DM*DM, n1 = NDIR*2*DI*DM, n2 = NDIR*DBL_W*DI, n3 = NDIR*DM*DI, n4 = 2*DM*4*DM;
        long i = (long)blk * 256 + tid;
        long off = 0;
        if (i < off + n0) { g_w_in_h[i - off] = __float2bfloat16(s0[i - off]); return; } off += n0;
        if (i < off + n1) { g_w_inproj_h[i - off] = __float2bfloat16(s1[i - off]); return; } off += n1;
        if (i < off + n2) { g_w_xp_h[i - off] = __float2bfloat16(s2[i - off]); return; } off += n2;
        if (i < off + n3) { g_w_out_h[i - off] = __float2bfloat16(s3[i - off]); return; } off += n3;
        if (i < off + n4) { g_w_f1_h[i - off] = __float2bfloat16(s4[i - off]); return; }
        return;
    }
    blk -= NWB;
    if (blk < B_OW) {                           // o_w -> bf16
        long i = (long)blk * 256 + tid;
        if (i < N_OW) g_w_ow_h[i] = __float2bfloat16(o_w[i]);
        return;
    }
    blk -= B_OW;
    if (blk < B_F2T) {                          // f_w2^T: [k][j] = f_w2[j][k]
        long i = (long)blk * 256 + tid;
        if (i < N_F2T) {
            int k = (int)(i / DM), j = (int)(i % DM);
            g_w_f2T[i] = __float2bfloat16(f_w2[j * (2 * DM) + k]);
        }
        return;
    }
    blk -= B_F2T;
    if (blk < 1) {                              // bc = o_w @ f_b2 + o_b
        if (tid < DM) {
            float acc = o_b[tid];
            const float* wr = o_w + (long)tid * DM;
            for (int j = 0; j < DM; j++) acc = fmaf(wr[j], f_b2[j], acc);
            g_cb[tid] = acc;
        }
        return;
    }
    blk -= 1;
    // ---- ln1 blocks ----
    {
        const int idx = blk;                    // 0..127
        const int b = idx >> 5, n0 = (idx & 31) << 5;
        float (*tile)[33] = (float(*)[33])sh;
        __shared__ float s_mean[32], s_rstd[32];

        for (int i = tid; i < DM * 32; i += 256) {
            int d = i >> 5, nn = i & 31;
            tile[d][nn] = x[((long)(b * DM + d) << 10) + n0 + nn];
        }
        __syncthreads();

        const int nn = tid >> 3, l = tid & 7;
        float s = 0.f, s2 = 0.f;
        for (int d = l; d < DM; d += 8) { float v = tile[d][nn]; s += v; s2 = fmaf(v, v, s2); }
        s  += __shfl_down_sync(0xffffffffu, s,  4, 8);
        s2 += __shfl_down_sync(0xffffffffu, s2, 4, 8);
        s  += __shfl_down_sync(0xffffffffu, s,  2, 8);
        s2 += __shfl_down_sync(0xffffffffu, s2, 2, 8);
        s  += __shfl_down_sync(0xffffffffu, s,  1, 8);
        s2 += __shfl_down_sync(0xffffffffu, s2, 1, 8);
        if (l == 0) {
            float m = s * (1.f / DM);
            float var = s2 * (1.f / DM) - m * m;
            s_mean[nn] = m;
            s_rstd[nn] = rsqrtf(var + 1e-5f);
        }
        __syncthreads();

        for (int i = tid; i < DM * 32; i += 256) {
            int nn2 = i / DM, d = i % DM;
            float v = (tile[d][nn2] - s_mean[nn2]) * s_rstd[nn2] * ng[d] + nb[d];
            long adr = ((long)(b << 10) + n0 + nn2) * DM + d;
            g_xs[adr] = v;
            g_xs_h[adr] = __float2bfloat16(v);
        }
    }
}

// ---------------- bf16 cp.async GEMM, BK=32, NST=4, peeled exact tail ----------------
// mode: 0 plain, 1 gather A rows via seq_src_n(z,.), 2 scatter C rows via seq_src_n(z,.)
template<int MFRAG, int NFRAG>
__global__ __launch_bounds__(256) void gemm_bf16_kernel(
    const bf16* __restrict__ A, const bf16* __restrict__ W,
    const float* __restrict__ bias, void* __restrict__ Cv,
    int M, int Nn, int K, int lda, int ldc,
    long sA_, long sW_, long sB_, long sC_, int act, int mode, int cbf)
{
    constexpr int TM = MFRAG * 32;
    constexpr int TN = NFRAG * 32;
    constexpr int PITCH = 40;
    const int z = blockIdx.z;
    A += z * sA_; W += z * sW_;
    const float* bz = bias ? (bias + z * sB_) : (const float*)0;

    __shared__ __align__(16) bf16 sA[4][TM][PITCH];
    __shared__ __align__(16) bf16 sB[4][TN][PITCH];
    constexpr uint32_t A_ST = TM * PITCH * 2;
    constexpr uint32_t B_ST = TN * PITCH * 2;

    const int bm = blockIdx.y * TM, bn = blockIdx.x * TN;
    const int tid = threadIdx.x;

    constexpr int TPR_A = 256 / TM;
    constexpr int NCP_A = 4 / TPR_A;
    constexpr int TPR_B = 256 / TN;
    constexpr int NCP_B = 4 / TPR_B;

    const int rA = tid / TPR_A;
    const int kA = (tid % TPR_A) * (NCP_A * 8);
    long arowi;
    if (mode == 1) {
        int gm = bm + rA;
        arowi = (long)(((gm >> 10) << 10) + seq_src_n(z, gm & 1023));
    } else {
        arowi = bm + rA;
    }
    const bf16* aPtr = A + arowi * lda + kA;
    const int rB = tid / TPR_B;
    const int kB = (tid % TPR_B) * (NCP_B * 8);
    const int gw_n = bn + rB;
    const bool wv = (gw_n < Nn);
    const bf16* wPtr = W + (wv ? (long)gw_n * K : 0) + kB;

    const uint32_t aDst0 = (uint32_t)__cvta_generic_to_shared(&sA[0][rA][kA]);
    const uint32_t bDst0 = (uint32_t)__cvta_generic_to_shared(&sB[0][rB][kB]);

    const int nkt = K >> 5;

    auto issue = [&](int kt) {
        const int s = kt & 3;
#pragma unroll
        for (int q = 0; q < NCP_A; q++)
            cp16(aDst0 + s * A_ST + q * 16, aPtr + (kt << 5) + q * 8, 16);
#pragma unroll
        for (int q = 0; q < NCP_B; q++)
            cp16(bDst0 + s * B_ST + q * 16, wPtr + (kt << 5) + q * 8, wv ? 16 : 0);
        cp_commit();
    };

    issue(0); issue(1); issue(2);

    float4 acc[MFRAG][NFRAG];
#pragma unroll
    for (int i = 0; i < MFRAG; i++)
#pragma unroll
        for (int j = 0; j < NFRAG; j++) acc[i][j] = make_float4(0.f, 0.f, 0.f, 0.f);

    const int lane = tid & 31, wid = tid >> 5;
    const int wm = wid >> 2, wn = wid & 3;

    const int a_row = wm * (MFRAG * 16) + (lane & 7) + (((lane >> 3) & 1) << 3);
    const int a_kc  = (lane >> 4) << 3;
    const uint32_t aAddr0 = (uint32_t)__cvta_generic_to_shared(&sA[0][a_row][a_kc]);
    const int b_row = wn * (NFRAG * 8) + (lane & 7) + ((lane >> 4) << 3);
    const int b_kc  = ((lane >> 3) & 1) << 3;
    const uint32_t bAddr0 = (uint32_t)__cvta_generic_to_shared(&sB[0][b_row][b_kc]);

    auto compute = [&](int kt) {
        const int s = kt & 3;
        const uint32_t aBase = aAddr0 + s * A_ST;
        const uint32_t bBase = bAddr0 + s * B_ST;
#pragma unroll
        for (int s2 = 0; s2 < 2; s2++) {
            const uint32_t aA = aBase + s2 * 32;
            const uint32_t bA = bBase + s2 * 32;
            uint32_t ra[MFRAG][4];
#pragma unroll
            for (int i = 0; i < MFRAG; i++)
                ldsm_x4(aA + i * (16 * PITCH * 2), ra[i][0], ra[i][1], ra[i][2], ra[i][3]);
            uint32_t rb[NFRAG][2];
#pragma unroll
            for (int jp = 0; jp < NFRAG / 2; jp++) {
                uint32_t b0, b1, b2, b3;
                ldsm_x4(bA + jp * (16 * PITCH * 2), b0, b1, b2, b3);
                rb[2 * jp][0] = b0; rb[2 * jp][1] = b1;
                rb[2 * jp + 1][0] = b2; rb[2 * jp + 1][1] = b3;
            }
#pragma unroll
            for (int i = 0; i < MFRAG; i++)
#pragma unroll
                for (int j = 0; j < NFRAG; j++)
                    mma_bf16(acc[i][j], ra[i][0], ra[i][1], ra[i][2], ra[i][3],
                             rb[j][0], rb[j][1]);
        }
    };

    int kt = 0;
    for (; kt < nkt - 3; kt++) {
        cp_wait2();
        __syncthreads();
        issue(kt + 3);
        compute(kt);
    }
    cp_wait2(); __syncthreads(); compute(kt); kt++;
    cp_wait1(); __syncthreads(); compute(kt); kt++;
    cp_wait0(); __syncthreads(); compute(kt);

    // ---- epilogue ----
    const int row0 = lane >> 2;
    const int col0 = (lane & 3) << 1;
    float* Cf = (float*)Cv + z * sC_;
    bf16*  Ch = (bf16*)Cv + z * sC_;
#pragma unroll
    for (int i = 0; i < MFRAG; i++) {
        const int gmA = bm + wm * (MFRAG * 16) + (i << 4) + row0;
        const int gmB = gmA + 8;
        long rAo, rBo;
        if (mode == 2) {
            rAo = ((gmA >> 10) << 10) + seq_src_n(z, gmA & 1023);
            rBo = ((gmB >> 10) << 10) + seq_src_n(z, gmB & 1023);
        } else { rAo = gmA; rBo = gmB; }
#pragma unroll
        for (int j = 0; j < NFRAG; j++) {
            const int gn = bn + wn * (NFRAG * 8) + (j << 3) + col0;
            if (gn < Nn) {
                float4 v = acc[i][j];
                if (bz) {
                    const float b0 = bz[gn], b1 = bz[gn + 1];
                    v.x += b0; v.y += b1; v.z += b0; v.w += b1;
                }
                if (act) {
                    v.x = apply_act(v.x, act); v.y = apply_act(v.y, act);
                    v.z = apply_act(v.z, act); v.w = apply_act(v.w, act);
                }
                if (cbf) {
                    *(uint32_t*)&Ch[rAo * (long)ldc + gn] = pack_bf2(v.x, v.y);
                    *(uint32_t*)&Ch[rBo * (long)ldc + gn] = pack_bf2(v.z, v.w);
                } else {
                    *(float2*)&Cf[rAo * (long)ldc + gn] = make_float2(v.x, v.y);
                    *(float2*)&Cf[rBo * (long)ldc + gn] = make_float2(v.z, v.w);
                }
            }
        }
    }
}

// ---------------- fused conv+silu+dbl GEMM ----------------
// Per block: 64 rows (t within one (d,b)), Nn=44 out, K=384.
// A rows = silu(conv(xz)) computed on the fly (also written to g_xsm_h).
// grid (64, NDIR): blockIdx.x = m-tile, blockIdx.y = direction.
__global__ __launch_bounds__(256) void dbl_conv_kernel(
    const float* __restrict__ cw, const float* __restrict__ cbb)
{
    constexpr int PITCH = 40;
    constexpr int NKT = 12;              // 384 / 32
    const int dd = blockIdx.y;
    const int bx = blockIdx.x;
    const int b = bx >> 4;               // batch
    const int tbase = (bx & 15) << 6;    // t of row 0
    const long sb = ((long)dd * BATCH + b) * NSEQ;
    const int tid = threadIdx.x;

    __shared__ __align__(16) bf16 sA[2][64][PITCH];
    __shared__ __align__(16) bf16 sB[4][64][PITCH];
    constexpr uint32_t A_ST = 64 * PITCH * 2;
    constexpr uint32_t B_ST = 64 * PITCH * 2;

    // staging geometry: 4 threads per row, 8 channels each per stage
    const int row = tid >> 2;
    const int chq = (tid & 3) << 3;      // channel offset within stage (0,8,16,24)
    const int t = tbase + row;
    const bf16* xzr = g_xz_h + (sb + t) * (2 * DI);
    bf16* xsr = g_xsm_h + (sb + t) * DI;

    // B: Wxp rows (Nn=44, zero-pad to 64)
    const int rB = tid >> 2;
    const int kB = (tid & 3) << 3;
    const bool wv = (rB < DBL_W);
    const bf16* wPtr = g_w_xp_h + (long)dd * DBL_W * DI + (wv ? (long)rB * DI : 0) + kB;
    const uint32_t bDst0 = (uint32_t)__cvta_generic_to_shared(&sB[0][rB][kB]);
    const uint32_t aDst0 = (uint32_t)__cvta_generic_to_shared(&sA[0][row][chq]);

    auto issueB = [&](int kt) {
        cp16(bDst0 + (kt & 3) * B_ST, wPtr + (kt << 5), wv ? 16 : 0);
        cp_commit();
    };

    uint4 v[4];
    auto loadA = [&](int s) {
        const int ch = chq + (s << 5);
#pragma unroll
        for (int j = 0; j < 4; j++) {
            if (t - j >= 0) v[j] = *(const uint4*)(xzr - (long)j * (2 * DI) + ch);
            else v[j] = make_uint4(0u, 0u, 0u, 0u);
        }
    };
    auto convStore = [&](int s) {
        const int ch = chq + (s << 5);
        float xv[4][8];
#pragma unroll
        for (int j = 0; j < 4; j++) {
            const __nv_bfloat162* p = (const __nv_bfloat162*)&v[j];
#pragma unroll
            for (int e = 0; e < 4; e++) {
                xv[j][2 * e]     = __bfloat162float(p[e].x);
                xv[j][2 * e + 1] = __bfloat162float(p[e].y);
            }
        }
        const float4* wrow = (const float4*)(cw + ((long)dd * DI + ch) * 4);
        const float* brow = cbb + dd * DI + ch;
        uint32_t outp[4];
#pragma unroll
        for (int e = 0; e < 4; e++) {
            float r[2];
#pragma unroll
            for (int h = 0; h < 2; h++) {
                const int q = 2 * e + h;
                const float4 w = wrow[q];
                float a = brow[q];
                a = fmaf(w.x, xv[3][q], a);
                a = fmaf(w.y, xv[2][q], a);
                a = fmaf(w.z, xv[1][q], a);
                a = fmaf(w.w, xv[0][q], a);
                r[h] = __fdividef(a, 1.f + __expf(-a));
            }
            outp[e] = pack_bf2(r[0], r[1]);
        }
        uint4 pk = make_uint4(outp[0], outp[1], outp[2], outp[3]);
        *(uint4*)((bf16*)sA + ((s & 1) * 64 * PITCH) + row * PITCH + chq) = pk;
        *(uint4*)(xsr + ch) = pk;
    };

    // prologue
    loadA(0); convStore(0);
    issueB(0); issueB(1); issueB(2);

    float4 acc[2][2];
#pragma unroll
    for (int i = 0; i < 2; i++)
#pragma unroll
        for (int j = 0; j < 2; j++) acc[i][j] = make_float4(0.f, 0.f, 0.f, 0.f);

    const int lane = tid & 31, wid = tid >> 5;
    const int wm = wid >> 2, wn = wid & 3;
    const int a_row = wm * 32 + (lane & 7) + (((lane >> 3) & 1) << 3);
    const int a_kc  = (lane >> 4) << 3;
    const uint32_t aAddr0 = (uint32_t)__cvta_generic_to_shared(&sA[0][a_row][a_kc]);
    const int b_row = wn * 16 + (lane & 7) + ((lane >> 4) << 3);
    const int b_kc  = ((lane >> 3) & 1) << 3;
    const uint32_t bAddr0 = (uint32_t)__cvta_generic_to_shared(&sB[0][b_row][b_kc]);

    auto compute = [&](int kt) {
        const uint32_t aBase = aAddr0 + (kt & 1) * A_ST;
        const uint32_t bBase = bAddr0 + (kt & 3) * B_ST;
#pragma unroll
        for (int s2 = 0; s2 < 2; s2++) {
            const uint32_t aA = aBase + s2 * 32;
            const uint32_t bA = bBase + s2 * 32;
            uint32_t ra[2][4];
#pragma unroll
            for (int i = 0; i < 2; i++)
                ldsm_x4(aA + i * (16 * PITCH * 2), ra[i][0], ra[i][1], ra[i][2], ra[i][3]);
            uint32_t b0, b1, b2, b3;
            ldsm_x4(bA, b0, b1, b2, b3);
#pragma unroll
            for (int i = 0; i < 2; i++) {
                mma_bf16(acc[i][0], ra[i][0], ra[i][1], ra[i][2], ra[i][3], b0, b1);
                mma_bf16(acc[i][1], ra[i][0], ra[i][1], ra[i][2], ra[i][3], b2, b3);
            }
        }
    };

    int kt = 0;
    for (; kt < NKT - 2; kt++) {           // kt = 0..9
        cp_wait2();
        __syncthreads();
        if (kt + 3 < NKT) issueB(kt + 3);
        loadA(kt + 1);
        compute(kt);
        convStore(kt + 1);
    }
    // kt = 10
    cp_wait1();
    __syncthreads();
    loadA(11);
    compute(10);
    convStore(11);
    // kt = 11
    cp_wait0();
    __syncthreads();
    compute(11);

    // ---- epilogue: fp32 dbl out, Nn = 44 ----
    const int row0 = lane >> 2;
    const int col0 = (lane & 3) << 1;
    float* Cf = g_dbl + ((long)dd * LROWS + (long)bx * 64) * DBL_W;
#pragma unroll
    for (int i = 0; i < 2; i++) {
        const int lmA = wm * 32 + (i << 4) + row0;
        const int lmB = lmA + 8;
#pragma unroll
        for (int j = 0; j < 2; j++) {
            const int gn = wn * 16 + (j << 3) + col0;
            if (gn < DBL_W) {
                float4 vv = acc[i][j];
                *(float2*)&Cf[(long)lmA * DBL_W + gn] = make_float2(vv.x, vv.y);
                *(float2*)&Cf[(long)lmB * DBL_W + gn] = make_float2(vv.z, vv.w);
            }
        }
    }
}

// ---------------- selective scan: fused dt-proj + power-chain dA ----------------
#define SCH 16
__global__ __launch_bounds__(256) void scan_kernel(
    const float* __restrict__ Alog, const float* __restrict__ Dp,
    const float* __restrict__ Wdt, const float* __restrict__ bdt)
{
    const int d = blockIdx.z, b = blockIdx.y;
    const int c0 = blockIdx.x << 6;
    const int tid = threadIdx.x;
    const int cl = tid >> 2;
    const int sg = tid & 3;
    const int c = c0 + cl;
    const long baseI = ((long)d * BATCH + b) * NSEQ;

    const bf16* xb   = g_xsm_h + baseI * DI       + c0;
    const bf16* zb   = g_xz_h  + baseI * (2 * DI) + DI + c0;
    const float* dblp = g_dbl + baseI * DBL_W;
    bf16* yb          = g_y_h + baseI * DI        + c0;

    __shared__ float s_wdt[64 * 13];
    __shared__ float s_bdt[64];
    __shared__ float s_raw[SCH * 12];
    __shared__ float s_bc [SCH * 32];
    __shared__ float s_dt [SCH * 64];
    __shared__ float s_x  [SCH * 64];
    __shared__ float s_g  [SCH * 64];

    for (int i = tid; i < 64 * DR; i += 256)
        s_wdt[(i / DR) * 13 + (i % DR)] = Wdt[((long)(d * DI + c0) + i / DR) * DR + (i % DR)];
    if (tid < 64) s_bdt[tid] = bdt[d * DI + c0 + tid];

    const float LOG2E = 1.44269504088896340736f;
    float Aa[4];
    bool fastf = true;
#pragma unroll
    for (int s = 0; s < 4; s++) {
        const float E = expf(Alog[((long)(d * DI + c)) * DS + (sg << 2) + s]);
        Aa[s] = -E * LOG2E;
        fastf = fastf && (fabsf(E - (float)((sg << 2) + s + 1)) < 1e-3f);
    }
    const float Dv = Dp[d * DI + c];

    float h[4];
#pragma unroll
    for (int s = 0; s < 4; s++) h[s] = 0.f;

    __syncthreads();

    for (int t0 = 0; t0 < NSEQ; t0 += SCH) {
        __syncthreads();
        if (tid < SCH * DR) s_raw[tid] = dblp[(long)(t0 + tid / DR) * DBL_W + (tid % DR)];
#pragma unroll
        for (int k = 0; k < 2; k++) {
            const int idx = tid + (k << 8);
            const int row = idx >> 5, col = idx & 31;
            s_bc[idx] = dblp[(long)(t0 + row) * DBL_W + DR + col];
        }
#pragma unroll
        for (int k = 0; k < 4; k++) {
            const int idx = tid + (k << 8);
            const int row = idx >> 6, col = idx & 63;
            s_x[idx] = __bfloat162float(xb[(long)(t0 + row) * DI + col]);
            const float zv = __bfloat162float(zb[(long)(t0 + row) * (2 * DI) + col]);
            s_g[idx] = __fdividef(zv, 1.f + __expf(-zv));
        }
        __syncthreads();
#pragma unroll
        for (int k = 0; k < 4; k++) {
            const int idx = tid + (k << 8);
            const int row = idx >> 6, col = idx & 63;
            float v = s_bdt[col];
#pragma unroll
            for (int j = 0; j < DR; j++)
                v = fmaf(s_raw[row * DR + j], s_wdt[col * 13 + j], v);
            s_dt[idx] = (v > 20.f) ? v : __logf(1.f + __expf(v));
        }
        __syncthreads();

        if (fastf) {
#pragma unroll
            for (int tt = 0; tt < SCH; tt++) {
                const float dt_v = s_dt[(tt << 6) + cl];
                const float x_v  = s_x [(tt << 6) + cl];
                const float* bc = s_bc + (tt << 5);
                const float dtx = dt_v * x_v;
                const float e1 = exp2f(-LOG2E * dt_v);
                const float e2 = e1 * e1, e3 = e2 * e1, e4 = e2 * e2;
                float eb = 1.f;
                if (sg & 1) eb = e4;
                const float e8 = e4 * e4;
                if (sg & 2) eb *= e8;
                const float dA0 = eb * e1, dA1 = eb * e2, dA2 = eb * e3, dA3 = eb * e4;
                float accv = 0.f;
                h[0] = fmaf(dA0, h[0], dtx * bc[(sg << 2) + 0]);
                accv = fmaf(h[0], bc[16 + (sg << 2) + 0], accv);
                h[1] = fmaf(dA1, h[1], dtx * bc[(sg << 2) + 1]);
                accv = fmaf(h[1], bc[16 + (sg << 2) + 1], accv);
                h[2] = fmaf(dA2, h[2], dtx * bc[(sg << 2) + 2]);
                accv = fmaf(h[2], bc[16 + (sg << 2) + 2], accv);
                h[3] = fmaf(dA3, h[3], dtx * bc[(sg << 2) + 3]);
                accv = fmaf(h[3], bc[16 + (sg << 2) + 3], accv);
                accv += __shfl_down_sync(0xffffffffu, accv, 2, 4);
                accv += __shfl_down_sync(0xffffffffu, accv, 1, 4);
                if (sg == 0) {
                    float yv = fmaf(x_v, Dv, accv);
                    yv *= s_g[(tt << 6) + cl];
                    yb[(long)(t0 + tt) * DI + cl] = __float2bfloat16(yv);
                }
            }
        } else {
#pragma unroll
            for (int tt = 0; tt < SCH; tt++) {
                const float dt_v = s_dt[(tt << 6) + cl];
                const float x_v  = s_x [(tt << 6) + cl];
                const float* bc = s_bc + (tt << 5);
                const float dtx = dt_v * x_v;
                float accv = 0.f;
#pragma unroll
                for (int s = 0; s < 4; s++) {
                    const float dA = exp2f(dt_v * Aa[s]);
                    h[s] = fmaf(dA, h[s], dtx * bc[(sg << 2) + s]);
                    accv = fmaf(h[s], bc[16 + (sg << 2) + s], accv);
                }
                accv += __shfl_down_sync(0xffffffffu, accv, 2, 4);
                accv += __shfl_down_sync(0xffffffffu, accv, 1, 4);
                if (sg == 0) {
                    float yv = fmaf(x_v, Dv, accv);
                    yv *= s_g[(tt << 6) + cl];
                    yb[(long)(t0 + tt) * DI + cl] = __float2bfloat16(yv);
                }
            }
        }
    }
}

// ---------------- final layernorm + residual + transpose-out ----------------
__global__ __launch_bounds__(256) void ln2_kernel(
    const float* __restrict__ g, const float* __restrict__ bb, float* __restrict__ out)
{
    __shared__ float t1[16][193];
    __shared__ float t2[16][193];
    __shared__ float s_mean[16], s_rstd[16];
    const int b = blockIdx.y, n0 = blockIdx.x << 4;
    const int tid = threadIdx.x;

    for (int i = tid; i < 16 * DM; i += 256) {
        int nn = i / DM, dd = i % DM;
        long adr = ((long)(b << 10) + n0 + nn) * DM + dd;
        t1[nn][dd] = g_h3[adr];
        t2[nn][dd] = g_xs[adr];
    }
    __syncthreads();

    const int nn = tid >> 4, l = tid & 15;
    float s = 0.f, s2 = 0.f;
    for (int dd = l; dd < DM; dd += 16) { float v = t1[nn][dd]; s += v; s2 = fmaf(v, v, s2); }
    s  += __shfl_down_sync(0xffffffffu, s,  8, 16);
    s2 += __shfl_down_sync(0xffffffffu, s2, 8, 16);
    s  += __shfl_down_sync(0xffffffffu, s,  4, 16);
    s2 += __shfl_down_sync(0xffffffffu, s2, 4, 16);
    s  += __shfl_down_sync(0xffffffffu, s,  2, 16);
    s2 += __shfl_down_sync(0xffffffffu, s2, 2, 16);
    s  += __shfl_down_sync(0xffffffffu, s,  1, 16);
    s2 += __shfl_down_sync(0xffffffffu, s2, 1, 16);
    if (l == 0) {
        float m = s * (1.f / DM);
        float var = s2 * (1.f / DM) - m * m;
        s_mean[nn] = m;
        s_rstd[nn] = rsqrtf(var + 1e-5f);
    }
    __syncthreads();

    for (int i = tid; i < DM * 16; i += 256) {
        int dd = i >> 4, nn2 = i & 15;
        float v = (t1[nn2][dd] - s_mean[nn2]) * s_rstd[nn2] * g[dd] + bb[dd] + t2[nn2][dd];
        out[((long)(b * DM + dd) << 10) + n0 + nn2] = v;
    }
}

// ---------------- launcher ----------------
extern "C" void kernel_launch(void* const* d_in, const int* in_sizes, int n_in,
                              void* d_out, int out_size)
{
    const float* x        = (const float*)d_in[0];
    const float* norm_g   = (const float*)d_in[1];
    const float* norm_b   = (const float*)d_in[2];
    const float* in_w     = (const float*)d_in[3];
    const float* in_b     = (const float*)d_in[4];
    const float* m_in_w   = (const float*)d_in[5];
    const float* m_conv_w = (const float*)d_in[6];
    const float* m_conv_b = (const float*)d_in[7];
    const float* m_xp_w   = (const float*)d_in[8];
    const float* m_dt_w   = (const float*)d_in[9];
    const float* m_dt_b   = (const float*)d_in[10];
    const float* m_Alog   = (const float*)d_in[11];
    const float* m_D      = (const float*)d_in[12];
    const float* m_out_w  = (const float*)d_in[13];
    const float* f_w1     = (const float*)d_in[14];
    const float* f_b1     = (const float*)d_in[15];
    const float* f_w2     = (const float*)d_in[16];
    const float* f_b2     = (const float*)d_in[17];
    const float* o_w      = (const float*)d_in[18];
    const float* o_b      = (const float*)d_in[19];
    const float* on_g     = (const float*)d_in[20];
    const float* on_b     = (const float*)d_in[21];
    float* out = (float*)d_out;

    float *p_dbl, *p_h3, *p_cb;
    bf16 *p_xs_h, *p_xp_h, *p_xz_h, *p_xsm_h, *p_y_h, *p_fused_h, *p_hdn_h;
    bf16 *p_w_in, *p_w_inproj, *p_w_xp, *p_w_out, *p_w_f1, *p_w_ow, *p_w_f2T, *p_cw_h;
    cudaGetSymbolAddress((void**)&p_dbl, g_dbl);
    cudaGetSymbolAddress((void**)&p_h3, g_h3);
    cudaGetSymbolAddress((void**)&p_cb, g_cb);
    cudaGetSymbolAddress((void**)&p_xs_h, g_xs_h);
    cudaGetSymbolAddress((void**)&p_xp_h, g_xp_h);
    cudaGetSymbolAddress((void**)&p_xz_h, g_xz_h);
    cudaGetSymbolAddress((void**)&p_xsm_h, g_xsm_h);
    cudaGetSymbolAddress((void**)&p_y_h, g_y_h);
    cudaGetSymbolAddress((void**)&p_fused_h, g_fused_h);
    cudaGetSymbolAddress((void**)&p_hdn_h, g_hdn_h);
    cudaGetSymbolAddress((void**)&p_w_in, g_w_in_h);
    cudaGetSymbolAddress((void**)&p_w_inproj, g_w_inproj_h);
    cudaGetSymbolAddress((void**)&p_w_xp, g_w_xp_h);
    cudaGetSymbolAddress((void**)&p_w_out, g_w_out_h);
    cudaGetSymbolAddress((void**)&p_w_f1, g_w_f1_h);
    cudaGetSymbolAddress((void**)&p_w_ow, g_w_ow_h);
    cudaGetSymbolAddress((void**)&p_w_f2T, g_w_f2T);
    cudaGetSymbolAddress((void**)&p_cw_h, g_cw_h);

    // 1) prep: conversions + transposes + bias + ln1
    prep_w_kernel<<<NWB + B_OW + B_F2T + 1 + NLN1, 256>>>(
        in_w, m_in_w, m_xp_w, m_out_w, f_w1,
        o_w, o_b, f_w2, f_b2, x, norm_g, norm_b);

    // 2) xp = xs @ in_w^T + in_b
    gemm_bf16_kernel<2, 2><<<dim3(3, 64, 1), 256>>>(p_xs_h, p_w_in, in_b, p_xp_h,
        LROWS, DM, DM, DM, DM, 0, 0, 0, 0, 0, 0, 1);

    // 3) xz[d] = gather_d(xp) @ m_in_w[d]^T
    gemm_bf16_kernel<4, 4><<<dim3(6, 32, 4), 256>>>(p_xp_h, p_w_inproj, nullptr, p_xz_h,
        LROWS, 2 * DI, DM, DM, 2 * DI,
        0, (long)2 * DI * DM, 0, (long)LROWS * 2 * DI, 0, 1, 1);

    // 4) fused conv+silu+dbl (captured by ncu)
    dbl_conv_kernel<<<dim3(64, NDIR), 256>>>(m_conv_w, m_conv_b);

    // 5) selective scan
    scan_kernel<<<dim3(6, BATCH, NDIR), 256>>>(m_Alog, m_D, m_dt_w, m_dt_b);

    // 6) fused[:, d*DM:(d+1)*DM] = scatter_d(y[d] @ m_out_w[d]^T)
    gemm_bf16_kernel<4, 2><<<dim3(3, 32, 4), 256>>>(p_y_h, p_w_out, nullptr, p_fused_h,
        LROWS, DM, DI, DI, 4 * DM,
        (long)LROWS * DI, (long)DM * DI, 0, (long)DM, 0, 2, 1);

    // 7) Wc = o_w @ f_w2 (bf16 GEMM)
    gemm_bf16_kernel<2, 2><<<dim3(6, 3, 1), 256>>>(p_w_ow, p_w_f2T, nullptr, p_cw_h,
        DM, 2 * DM, DM, DM, 2 * DM, 0, 0, 0, 0, 0, 0, 1);

    // 8) hdn = gelu(fused @ f_w1^T + f_b1)
    gemm_bf16_kernel<4, 2><<<dim3(6, 32, 1), 256>>>(p_fused_h, p_w_f1, f_b1, p_hdn_h,
        LROWS, 2 * DM, 4 * DM, 4 * DM, 2 * DM, 0, 0, 0, 0, 2, 0, 1);

    // 9) h3 = hdn @ Wc^T + bc
    gemm_bf16_kernel<2, 2><<<dim3(3, 64, 1), 256>>>(p_hdn_h, p_cw_h, p_cb, p_h3,
        LROWS, DM, 2 * DM, 2 * DM, DM, 0, 0, 0, 0, 0, 0, 0);

    // 10) final layernorm + residual + transpose out
    ln2_kernel<<<dim3(64, 4), 256>>>(on_g, on_b, out);
}

// round 15
// speedup vs baseline: 1.0376x; 1.0376x over previous
#include <cuda_runtime.h>
#include <cuda_bf16.h>
#include <math.h>
#include <stdint.h>

// ---------------- problem constants ----------------
#define BATCH 4
#define DM    192
#define DI    384
#define DS    16
#define DR    12
#define NSEQ  1024
#define LROWS 4096
#define NDIR  4
#define DBL_W 44

typedef __nv_bfloat16 bf16;

// ---------------- scratch ----------------
__device__ float g_xs  [LROWS*DM];
__device__ float g_dbl [NDIR*LROWS*DBL_W];
__device__ float g_h3  [LROWS*DM];
__device__ float g_cb  [DM];

__device__ bf16 g_xs_h  [LROWS*DM];
__device__ bf16 g_xp_h  [LROWS*DM];
__device__ bf16 g_xz_h  [(long)NDIR*LROWS*2*DI];
__device__ bf16 g_xsm_h [NDIR*LROWS*DI];
__device__ bf16 g_y_h   [NDIR*LROWS*DI];
__device__ bf16 g_fused_h[LROWS*4*DM];
__device__ bf16 g_hdn_h [LROWS*2*DM];

__device__ bf16 g_w_in_h    [DM*DM];
__device__ bf16 g_w_inproj_h[NDIR*2*DI*DM];
__device__ bf16 g_w_xp_h    [NDIR*DBL_W*DI];
__device__ bf16 g_w_out_h   [NDIR*DM*DI];
__device__ bf16 g_w_f1_h    [2*DM*4*DM];
__device__ bf16 g_w_ow_h    [DM*DM];          // o_w bf16
__device__ bf16 g_w_f2T     [2*DM*DM];        // f_w2^T bf16
__device__ bf16 g_cw_h      [DM*2*DM];        // o_w @ f_w2 (bf16, via GEMM)

// ---------------- helpers ----------------
__device__ __forceinline__ float apply_act(float v, int act) {
    if (act == 1) {
        v = (v > 20.f) ? v : __logf(1.f + __expf(v));
    } else if (act == 2) {
        v = 0.5f * v * (1.f + erff(v * 0.70710678118654752f));
    }
    return v;
}

__device__ __forceinline__ int seq_src_n(int d, int t) {
    if (d == 0) return t;
    if (d == 1) return NSEQ - 1 - t;
    if (d == 2) return ((t & 31) << 5) + (t >> 5);
    int u = NSEQ - 1 - t;
    return ((u & 31) << 5) + (u >> 5);
}

__device__ __forceinline__ void mma_bf16(float4& c,
    uint32_t a0, uint32_t a1, uint32_t a2, uint32_t a3, uint32_t b0, uint32_t b1) {
    asm volatile(
        "mma.sync.aligned.m16n8k16.row.col.f32.bf16.bf16.f32 "
        "{%0,%1,%2,%3}, {%4,%5,%6,%7}, {%8,%9}, {%0,%1,%2,%3};\n"
        : "+f"(c.x), "+f"(c.y), "+f"(c.z), "+f"(c.w)
        : "r"(a0), "r"(a1), "r"(a2), "r"(a3), "r"(b0), "r"(b1));
}

__device__ __forceinline__ void ldsm_x4(uint32_t addr,
    uint32_t& r0, uint32_t& r1, uint32_t& r2, uint32_t& r3) {
    asm volatile("ldmatrix.sync.aligned.m8n8.x4.shared.b16 {%0,%1,%2,%3}, [%4];"
        : "=r"(r0), "=r"(r1), "=r"(r2), "=r"(r3) : "r"(addr));
}

__device__ __forceinline__ uint32_t pack_bf2(float lo, float hi) {
    __nv_bfloat162 p = __floats2bfloat162_rn(lo, hi);
    return *(uint32_t*)&p;
}

__device__ __forceinline__ void cp16(uint32_t saddr, const void* gptr, int src_bytes) {
    asm volatile("cp.async.cg.shared.global [%0], [%1], 16, %2;\n"
        :: "r"(saddr), "l"(gptr), "r"(src_bytes));
}
__device__ __forceinline__ void cp_commit() {
    asm volatile("cp.async.commit_group;\n");
}
__device__ __forceinline__ void cp_wait2() { asm volatile("cp.async.wait_group 2;\n"); }
__device__ __forceinline__ void cp_wait1() { asm volatile("cp.async.wait_group 1;\n"); }
__device__ __forceinline__ void cp_wait0() { asm volatile("cp.async.wait_group 0;\n"); }

// ---------------- prep: conversions + transposes + bias + ln1 (one launch) ----------------
#define N_WCONV (DM*DM + NDIR*2*DI*DM + NDIR*DBL_W*DI + NDIR*DM*DI + 2*DM*4*DM)
#define NWB ((N_WCONV + 255) / 256)
#define N_OW  (DM*DM)
#define N_F2T (2*DM*DM)
#define B_OW  ((N_OW + 255) / 256)
#define B_F2T ((N_F2T + 255) / 256)
#define NLN1 128

__global__ __launch_bounds__(256) void prep_w_kernel(
    const float* s0, const float* s1, const float* s2, const float* s3, const float* s4,
    const float* __restrict__ o_w, const float* __restrict__ o_b,
    const float* __restrict__ f_w2, const float* __restrict__ f_b2,
    const float* __restrict__ x, const float* __restrict__ ng, const float* __restrict__ nb)
{
    __shared__ float sh[DM * 33 + 64];
    const int tid = threadIdx.x;
    int blk = blockIdx.x;

    if (blk < NWB) {
        const int n0 = DM*DM, n1 = NDIR*2*DI*DM, n2 = NDIR*DBL_W*DI, n3 = NDIR*DM*DI, n4 = 2*DM*4*DM;
        long i = (long)blk * 256 + tid;
        long off = 0;
        if (i < off + n0) { g_w_in_h[i - off] = __float2bfloat16(s0[i - off]); return; } off += n0;
        if (i < off + n1) { g_w_inproj_h[i - off] = __float2bfloat16(s1[i - off]); return; } off += n1;
        if (i < off + n2) { g_w_xp_h[i - off] = __float2bfloat16(s2[i - off]); return; } off += n2;
        if (i < off + n3) { g_w_out_h[i - off] = __float2bfloat16(s3[i - off]); return; } off += n3;
        if (i < off + n4) { g_w_f1_h[i - off] = __float2bfloat16(s4[i - off]); return; }
        return;
    }
    blk -= NWB;
    if (blk < B_OW) {                           // o_w -> bf16
        long i = (long)blk * 256 + tid;
        if (i < N_OW) g_w_ow_h[i] = __float2bfloat16(o_w[i]);
        return;
    }
    blk -= B_OW;
    if (blk < B_F2T) {                          // f_w2^T: [k][j] = f_w2[j][k]
        long i = (long)blk * 256 + tid;
        if (i < N_F2T) {
            int k = (int)(i / DM), j = (int)(i % DM);
            g_w_f2T[i] = __float2bfloat16(f_w2[j * (2 * DM) + k]);
        }
        return;
    }
    blk -= B_F2T;
    if (blk < 1) {                              // bc = o_w @ f_b2 + o_b
        if (tid < DM) {
            float acc = o_b[tid];
            const float* wr = o_w + (long)tid * DM;
            for (int j = 0; j < DM; j++) acc = fmaf(wr[j], f_b2[j], acc);
            g_cb[tid] = acc;
        }
        return;
    }
    blk -= 1;
    // ---- ln1 blocks ----
    {
        const int idx = blk;                    // 0..127
        const int b = idx >> 5, n0 = (idx & 31) << 5;
        float (*tile)[33] = (float(*)[33])sh;
        __shared__ float s_mean[32], s_rstd[32];

        for (int i = tid; i < DM * 32; i += 256) {
            int d = i >> 5, nn = i & 31;
            tile[d][nn] = x[((long)(b * DM + d) << 10) + n0 + nn];
        }
        __syncthreads();

        const int nn = tid >> 3, l = tid & 7;
        float s = 0.f, s2 = 0.f;
        for (int d = l; d < DM; d += 8) { float v = tile[d][nn]; s += v; s2 = fmaf(v, v, s2); }
        s  += __shfl_down_sync(0xffffffffu, s,  4, 8);
        s2 += __shfl_down_sync(0xffffffffu, s2, 4, 8);
        s  += __shfl_down_sync(0xffffffffu, s,  2, 8);
        s2 += __shfl_down_sync(0xffffffffu, s2, 2, 8);
        s  += __shfl_down_sync(0xffffffffu, s,  1, 8);
        s2 += __shfl_down_sync(0xffffffffu, s2, 1, 8);
        if (l == 0) {
            float m = s * (1.f / DM);
            float var = s2 * (1.f / DM) - m * m;
            s_mean[nn] = m;
            s_rstd[nn] = rsqrtf(var + 1e-5f);
        }
        __syncthreads();

        for (int i = tid; i < DM * 32; i += 256) {
            int nn2 = i / DM, d = i % DM;
            float v = (tile[d][nn2] - s_mean[nn2]) * s_rstd[nn2] * ng[d] + nb[d];
            long adr = ((long)(b << 10) + n0 + nn2) * DM + d;
            g_xs[adr] = v;
            g_xs_h[adr] = __float2bfloat16(v);
        }
    }
}

// ---------------- bf16 cp.async GEMM, BK=32, NST=4, peeled exact tail ----------------
// mode: 0 plain, 1 gather A rows via seq_src_n(z,.), 2 scatter C rows via seq_src_n(z,.)
template<int MFRAG, int NFRAG>
__global__ __launch_bounds__(256) void gemm_bf16_kernel(
    const bf16* __restrict__ A, const bf16* __restrict__ W,
    const float* __restrict__ bias, void* __restrict__ Cv,
    int M, int Nn, int K, int lda, int ldc,
    long sA_, long sW_, long sB_, long sC_, int act, int mode, int cbf)
{
    constexpr int TM = MFRAG * 32;
    constexpr int TN = NFRAG * 32;
    constexpr int PITCH = 40;
    const int z = blockIdx.z;
    A += z * sA_; W += z * sW_;
    const float* bz = bias ? (bias + z * sB_) : (const float*)0;

    __shared__ __align__(16) bf16 sA[4][TM][PITCH];
    __shared__ __align__(16) bf16 sB[4][TN][PITCH];
    constexpr uint32_t A_ST = TM * PITCH * 2;
    constexpr uint32_t B_ST = TN * PITCH * 2;

    const int bm = blockIdx.y * TM, bn = blockIdx.x * TN;
    const int tid = threadIdx.x;

    constexpr int TPR_A = 256 / TM;
    constexpr int NCP_A = 4 / TPR_A;
    constexpr int TPR_B = 256 / TN;
    constexpr int NCP_B = 4 / TPR_B;

    const int rA = tid / TPR_A;
    const int kA = (tid % TPR_A) * (NCP_A * 8);
    long arowi;
    if (mode == 1) {
        int gm = bm + rA;
        arowi = (long)(((gm >> 10) << 10) + seq_src_n(z, gm & 1023));
    } else {
        arowi = bm + rA;
    }
    const bf16* aPtr = A + arowi * lda + kA;
    const int rB = tid / TPR_B;
    const int kB = (tid % TPR_B) * (NCP_B * 8);
    const int gw_n = bn + rB;
    const bool wv = (gw_n < Nn);
    const bf16* wPtr = W + (wv ? (long)gw_n * K : 0) + kB;

    const uint32_t aDst0 = (uint32_t)__cvta_generic_to_shared(&sA[0][rA][kA]);
    const uint32_t bDst0 = (uint32_t)__cvta_generic_to_shared(&sB[0][rB][kB]);

    const int nkt = K >> 5;

    auto issue = [&](int kt) {
        const int s = kt & 3;
#pragma unroll
        for (int q = 0; q < NCP_A; q++)
            cp16(aDst0 + s * A_ST + q * 16, aPtr + (kt << 5) + q * 8, 16);
#pragma unroll
        for (int q = 0; q < NCP_B; q++)
            cp16(bDst0 + s * B_ST + q * 16, wPtr + (kt << 5) + q * 8, wv ? 16 : 0);
        cp_commit();
    };

    issue(0); issue(1); issue(2);

    float4 acc[MFRAG][NFRAG];
#pragma unroll
    for (int i = 0; i < MFRAG; i++)
#pragma unroll
        for (int j = 0; j < NFRAG; j++) acc[i][j] = make_float4(0.f, 0.f, 0.f, 0.f);

    const int lane = tid & 31, wid = tid >> 5;
    const int wm = wid >> 2, wn = wid & 3;

    const int a_row = wm * (MFRAG * 16) + (lane & 7) + (((lane >> 3) & 1) << 3);
    const int a_kc  = (lane >> 4) << 3;
    const uint32_t aAddr0 = (uint32_t)__cvta_generic_to_shared(&sA[0][a_row][a_kc]);
    const int b_row = wn * (NFRAG * 8) + (lane & 7) + ((lane >> 4) << 3);
    const int b_kc  = ((lane >> 3) & 1) << 3;
    const uint32_t bAddr0 = (uint32_t)__cvta_generic_to_shared(&sB[0][b_row][b_kc]);

    auto compute = [&](int kt) {
        const int s = kt & 3;
        const uint32_t aBase = aAddr0 + s * A_ST;
        const uint32_t bBase = bAddr0 + s * B_ST;
#pragma unroll
        for (int s2 = 0; s2 < 2; s2++) {
            const uint32_t aA = aBase + s2 * 32;
            const uint32_t bA = bBase + s2 * 32;
            uint32_t ra[MFRAG][4];
#pragma unroll
            for (int i = 0; i < MFRAG; i++)
                ldsm_x4(aA + i * (16 * PITCH * 2), ra[i][0], ra[i][1], ra[i][2], ra[i][3]);
            uint32_t rb[NFRAG][2];
#pragma unroll
            for (int jp = 0; jp < NFRAG / 2; jp++) {
                uint32_t b0, b1, b2, b3;
                ldsm_x4(bA + jp * (16 * PITCH * 2), b0, b1, b2, b3);
                rb[2 * jp][0] = b0; rb[2 * jp][1] = b1;
                rb[2 * jp + 1][0] = b2; rb[2 * jp + 1][1] = b3;
            }
#pragma unroll
            for (int i = 0; i < MFRAG; i++)
#pragma unroll
                for (int j = 0; j < NFRAG; j++)
                    mma_bf16(acc[i][j], ra[i][0], ra[i][1], ra[i][2], ra[i][3],
                             rb[j][0], rb[j][1]);
        }
    };

    int kt = 0;
    for (; kt < nkt - 3; kt++) {
        cp_wait2();
        __syncthreads();
        issue(kt + 3);
        compute(kt);
    }
    cp_wait2(); __syncthreads(); compute(kt); kt++;
    cp_wait1(); __syncthreads(); compute(kt); kt++;
    cp_wait0(); __syncthreads(); compute(kt);

    // ---- epilogue ----
    const int row0 = lane >> 2;
    const int col0 = (lane & 3) << 1;
    float* Cf = (float*)Cv + z * sC_;
    bf16*  Ch = (bf16*)Cv + z * sC_;
#pragma unroll
    for (int i = 0; i < MFRAG; i++) {
        const int gmA = bm + wm * (MFRAG * 16) + (i << 4) + row0;
        const int gmB = gmA + 8;
        long rAo, rBo;
        if (mode == 2) {
            rAo = ((gmA >> 10) << 10) + seq_src_n(z, gmA & 1023);
            rBo = ((gmB >> 10) << 10) + seq_src_n(z, gmB & 1023);
        } else { rAo = gmA; rBo = gmB; }
#pragma unroll
        for (int j = 0; j < NFRAG; j++) {
            const int gn = bn + wn * (NFRAG * 8) + (j << 3) + col0;
            if (gn < Nn) {
                float4 v = acc[i][j];
                if (bz) {
                    const float b0 = bz[gn], b1 = bz[gn + 1];
                    v.x += b0; v.y += b1; v.z += b0; v.w += b1;
                }
                if (act) {
                    v.x = apply_act(v.x, act); v.y = apply_act(v.y, act);
                    v.z = apply_act(v.z, act); v.w = apply_act(v.w, act);
                }
                if (cbf) {
                    *(uint32_t*)&Ch[rAo * (long)ldc + gn] = pack_bf2(v.x, v.y);
                    *(uint32_t*)&Ch[rBo * (long)ldc + gn] = pack_bf2(v.z, v.w);
                } else {
                    *(float2*)&Cf[rAo * (long)ldc + gn] = make_float2(v.x, v.y);
                    *(float2*)&Cf[rBo * (long)ldc + gn] = make_float2(v.z, v.w);
                }
            }
        }
    }
}

// ---------------- causal depthwise conv + silu, 2 channels per thread ----------------
__global__ __launch_bounds__(256) void conv_silu_kernel(
    const float* __restrict__ cw, const float* __restrict__ cb)
{
    const int gi = blockIdx.x * 256 + threadIdx.x;      // < 16*64*192
    const int cp = gi % 192;
    const int c = cp << 1;
    const int rest = gi / 192;
    const int tb = rest & 63;
    const int db = rest >> 6;
    const int d = db >> 2;
    const int t0 = tb << 4;

    const float* wp = cw + ((long)d * DI + c) * 4;
    const float wa0 = wp[0], wa1 = wp[1], wa2 = wp[2], wa3 = wp[3];
    const float wb0 = wp[4], wb1 = wp[5], wb2 = wp[6], wb3 = wp[7];
    const float ba = cb[d * DI + c];
    const float bb_ = cb[d * DI + c + 1];
    const bf16* src = g_xz_h + ((long)db * NSEQ) * (2 * DI) + c;
    bf16* dst = g_xsm_h + ((long)db * NSEQ) * DI + c;

    auto ld2 = [&](int t) -> float2 {
        __nv_bfloat162 v = *(const __nv_bfloat162*)&src[(long)t * (2 * DI)];
        return make_float2(__bfloat162float(v.x), __bfloat162float(v.y));
    };
    float2 r0 = (t0 >= 3) ? ld2(t0 - 3) : make_float2(0.f, 0.f);
    float2 r1 = (t0 >= 2) ? ld2(t0 - 2) : make_float2(0.f, 0.f);
    float2 r2 = (t0 >= 1) ? ld2(t0 - 1) : make_float2(0.f, 0.f);
#pragma unroll
    for (int i = 0; i < 16; i++) {
        const int t = t0 + i;
        const float2 cur = ld2(t);
        float a = ba;
        a = fmaf(wa0, r0.x, a); a = fmaf(wa1, r1.x, a);
        a = fmaf(wa2, r2.x, a); a = fmaf(wa3, cur.x, a);
        float b = bb_;
        b = fmaf(wb0, r0.y, b); b = fmaf(wb1, r1.y, b);
        b = fmaf(wb2, r2.y, b); b = fmaf(wb3, cur.y, b);
        a = __fdividef(a, 1.f + __expf(-a));
        b = __fdividef(b, 1.f + __expf(-b));
        *(uint32_t*)&dst[(long)t * DI] = pack_bf2(a, b);
        r0 = r1; r1 = r2; r2 = cur;
    }
}

// ---------------- selective scan: fused dt-proj + power-chain dA ----------------
#define SCH 16
__global__ __launch_bounds__(256) void scan_kernel(
    const float* __restrict__ Alog, const float* __restrict__ Dp,
    const float* __restrict__ Wdt, const float* __restrict__ bdt)
{
    const int d = blockIdx.z, b = blockIdx.y;
    const int c0 = blockIdx.x << 6;
    const int tid = threadIdx.x;
    const int cl = tid >> 2;
    const int sg = tid & 3;
    const int c = c0 + cl;
    const long baseI = ((long)d * BATCH + b) * NSEQ;

    const bf16* xb   = g_xsm_h + baseI * DI       + c0;
    const bf16* zb   = g_xz_h  + baseI * (2 * DI) + DI + c0;
    const float* dblp = g_dbl + baseI * DBL_W;
    bf16* yb          = g_y_h + baseI * DI        + c0;

    __shared__ float s_wdt[64 * 13];
    __shared__ float s_bdt[64];
    __shared__ float s_raw[SCH * 12];
    __shared__ float s_bc [SCH * 32];
    __shared__ float s_dt [SCH * 64];
    __shared__ float s_x  [SCH * 64];
    __shared__ float s_g  [SCH * 64];

    for (int i = tid; i < 64 * DR; i += 256)
        s_wdt[(i / DR) * 13 + (i % DR)] = Wdt[((long)(d * DI + c0) + i / DR) * DR + (i % DR)];
    if (tid < 64) s_bdt[tid] = bdt[d * DI + c0 + tid];

    const float LOG2E = 1.44269504088896340736f;
    float Aa[4];
    bool fastf = true;
#pragma unroll
    for (int s = 0; s < 4; s++) {
        const float E = expf(Alog[((long)(d * DI + c)) * DS + (sg << 2) + s]);
        Aa[s] = -E * LOG2E;
        fastf = fastf && (fabsf(E - (float)((sg << 2) + s + 1)) < 1e-3f);
    }
    const float Dv = Dp[d * DI + c];

    float h[4];
#pragma unroll
    for (int s = 0; s < 4; s++) h[s] = 0.f;

    __syncthreads();

    for (int t0 = 0; t0 < NSEQ; t0 += SCH) {
        __syncthreads();
        if (tid < SCH * DR) s_raw[tid] = dblp[(long)(t0 + tid / DR) * DBL_W + (tid % DR)];
#pragma unroll
        for (int k = 0; k < 2; k++) {
            const int idx = tid + (k << 8);
            const int row = idx >> 5, col = idx & 31;
            s_bc[idx] = dblp[(long)(t0 + row) * DBL_W + DR + col];
        }
#pragma unroll
        for (int k = 0; k < 4; k++) {
            const int idx = tid + (k << 8);
            const int row = idx >> 6, col = idx & 63;
            s_x[idx] = __bfloat162float(xb[(long)(t0 + row) * DI + col]);
            const float zv = __bfloat162float(zb[(long)(t0 + row) * (2 * DI) + col]);
            s_g[idx] = __fdividef(zv, 1.f + __expf(-zv));
        }
        __syncthreads();
#pragma unroll
        for (int k = 0; k < 4; k++) {
            const int idx = tid + (k << 8);
            const int row = idx >> 6, col = idx & 63;
            float v = s_bdt[col];
#pragma unroll
            for (int j = 0; j < DR; j++)
                v = fmaf(s_raw[row * DR + j], s_wdt[col * 13 + j], v);
            s_dt[idx] = (v > 20.f) ? v : __logf(1.f + __expf(v));
        }
        __syncthreads();

        if (fastf) {
#pragma unroll
            for (int tt = 0; tt < SCH; tt++) {
                const float dt_v = s_dt[(tt << 6) + cl];
                const float x_v  = s_x [(tt << 6) + cl];
                const float* bc = s_bc + (tt << 5);
                const float dtx = dt_v * x_v;
                const float e1 = exp2f(-LOG2E * dt_v);
                const float e2 = e1 * e1, e3 = e2 * e1, e4 = e2 * e2;
                float eb = 1.f;
                if (sg & 1) eb = e4;
                const float e8 = e4 * e4;
                if (sg & 2) eb *= e8;
                const float dA0 = eb * e1, dA1 = eb * e2, dA2 = eb * e3, dA3 = eb * e4;
                float accv = 0.f;
                h[0] = fmaf(dA0, h[0], dtx * bc[(sg << 2) + 0]);
                accv = fmaf(h[0], bc[16 + (sg << 2) + 0], accv);
                h[1] = fmaf(dA1, h[1], dtx * bc[(sg << 2) + 1]);
                accv = fmaf(h[1], bc[16 + (sg << 2) + 1], accv);
                h[2] = fmaf(dA2, h[2], dtx * bc[(sg << 2) + 2]);
                accv = fmaf(h[2], bc[16 + (sg << 2) + 2], accv);
                h[3] = fmaf(dA3, h[3], dtx * bc[(sg << 2) + 3]);
                accv = fmaf(h[3], bc[16 + (sg << 2) + 3], accv);
                accv += __shfl_down_sync(0xffffffffu, accv, 2, 4);
                accv += __shfl_down_sync(0xffffffffu, accv, 1, 4);
                if (sg == 0) {
                    float yv = fmaf(x_v, Dv, accv);
                    yv *= s_g[(tt << 6) + cl];
                    yb[(long)(t0 + tt) * DI + cl] = __float2bfloat16(yv);
                }
            }
        } else {
#pragma unroll
            for (int tt = 0; tt < SCH; tt++) {
                const float dt_v = s_dt[(tt << 6) + cl];
                const float x_v  = s_x [(tt << 6) + cl];
                const float* bc = s_bc + (tt << 5);
                const float dtx = dt_v * x_v;
                float accv = 0.f;
#pragma unroll
                for (int s = 0; s < 4; s++) {
                    const float dA = exp2f(dt_v * Aa[s]);
                    h[s] = fmaf(dA, h[s], dtx * bc[(sg << 2) + s]);
                    accv = fmaf(h[s], bc[16 + (sg << 2) + s], accv);
                }
                accv += __shfl_down_sync(0xffffffffu, accv, 2, 4);
                accv += __shfl_down_sync(0xffffffffu, accv, 1, 4);
                if (sg == 0) {
                    float yv = fmaf(x_v, Dv, accv);
                    yv *= s_g[(tt << 6) + cl];
                    yb[(long)(t0 + tt) * DI + cl] = __float2bfloat16(yv);
                }
            }
        }
    }
}

// ---------------- final layernorm + residual + transpose-out ----------------
__global__ __launch_bounds__(256) void ln2_kernel(
    const float* __restrict__ g, const float* __restrict__ bb, float* __restrict__ out)
{
    __shared__ float t1[16][193];
    __shared__ float t2[16][193];
    __shared__ float s_mean[16], s_rstd[16];
    const int b = blockIdx.y, n0 = blockIdx.x << 4;
    const int tid = threadIdx.x;

    for (int i = tid; i < 16 * DM; i += 256) {
        int nn = i / DM, dd = i % DM;
        long adr = ((long)(b << 10) + n0 + nn) * DM + dd;
        t1[nn][dd] = g_h3[adr];
        t2[nn][dd] = g_xs[adr];
    }
    __syncthreads();

    const int nn = tid >> 4, l = tid & 15;
    float s = 0.f, s2 = 0.f;
    for (int dd = l; dd < DM; dd += 16) { float v = t1[nn][dd]; s += v; s2 = fmaf(v, v, s2); }
    s  += __shfl_down_sync(0xffffffffu, s,  8, 16);
    s2 += __shfl_down_sync(0xffffffffu, s2, 8, 16);
    s  += __shfl_down_sync(0xffffffffu, s,  4, 16);
    s2 += __shfl_down_sync(0xffffffffu, s2, 4, 16);
    s  += __shfl_down_sync(0xffffffffu, s,  2, 16);
    s2 += __shfl_down_sync(0xffffffffu, s2, 2, 16);
    s  += __shfl_down_sync(0xffffffffu, s,  1, 16);
    s2 += __shfl_down_sync(0xffffffffu, s2, 1, 16);
    if (l == 0) {
        float m = s * (1.f / DM);
        float var = s2 * (1.f / DM) - m * m;
        s_mean[nn] = m;
        s_rstd[nn] = rsqrtf(var + 1e-5f);
    }
    __syncthreads();

    for (int i = tid; i < DM * 16; i += 256) {
        int dd = i >> 4, nn2 = i & 15;
        float v = (t1[nn2][dd] - s_mean[nn2]) * s_rstd[nn2] * g[dd] + bb[dd] + t2[nn2][dd];
        out[((long)(b * DM + dd) << 10) + n0 + nn2] = v;
    }
}

// ---------------- launcher ----------------
extern "C" void kernel_launch(void* const* d_in, const int* in_sizes, int n_in,
                              void* d_out, int out_size)
{
    const float* x        = (const float*)d_in[0];
    const float* norm_g   = (const float*)d_in[1];
    const float* norm_b   = (const float*)d_in[2];
    const float* in_w     = (const float*)d_in[3];
    const float* in_b     = (const float*)d_in[4];
    const float* m_in_w   = (const float*)d_in[5];
    const float* m_conv_w = (const float*)d_in[6];
    const float* m_conv_b = (const float*)d_in[7];
    const float* m_xp_w   = (const float*)d_in[8];
    const float* m_dt_w   = (const float*)d_in[9];
    const float* m_dt_b   = (const float*)d_in[10];
    const float* m_Alog   = (const float*)d_in[11];
    const float* m_D      = (const float*)d_in[12];
    const float* m_out_w  = (const float*)d_in[13];
    const float* f_w1     = (const float*)d_in[14];
    const float* f_b1     = (const float*)d_in[15];
    const float* f_w2     = (const float*)d_in[16];
    const float* f_b2     = (const float*)d_in[17];
    const float* o_w      = (const float*)d_in[18];
    const float* o_b      = (const float*)d_in[19];
    const float* on_g     = (const float*)d_in[20];
    const float* on_b     = (const float*)d_in[21];
    float* out = (float*)d_out;

    float *p_dbl, *p_h3, *p_cb;
    bf16 *p_xs_h, *p_xp_h, *p_xz_h, *p_xsm_h, *p_y_h, *p_fused_h, *p_hdn_h;
    bf16 *p_w_in, *p_w_inproj, *p_w_xp, *p_w_out, *p_w_f1, *p_w_ow, *p_w_f2T, *p_cw_h;
    cudaGetSymbolAddress((void**)&p_dbl, g_dbl);
    cudaGetSymbolAddress((void**)&p_h3, g_h3);
    cudaGetSymbolAddress((void**)&p_cb, g_cb);
    cudaGetSymbolAddress((void**)&p_xs_h, g_xs_h);
    cudaGetSymbolAddress((void**)&p_xp_h, g_xp_h);
    cudaGetSymbolAddress((void**)&p_xz_h, g_xz_h);
    cudaGetSymbolAddress((void**)&p_xsm_h, g_xsm_h);
    cudaGetSymbolAddress((void**)&p_y_h, g_y_h);
    cudaGetSymbolAddress((void**)&p_fused_h, g_fused_h);
    cudaGetSymbolAddress((void**)&p_hdn_h, g_hdn_h);
    cudaGetSymbolAddress((void**)&p_w_in, g_w_in_h);
    cudaGetSymbolAddress((void**)&p_w_inproj, g_w_inproj_h);
    cudaGetSymbolAddress((void**)&p_w_xp, g_w_xp_h);
    cudaGetSymbolAddress((void**)&p_w_out, g_w_out_h);
    cudaGetSymbolAddress((void**)&p_w_f1, g_w_f1_h);
    cudaGetSymbolAddress((void**)&p_w_ow, g_w_ow_h);
    cudaGetSymbolAddress((void**)&p_w_f2T, g_w_f2T);
    cudaGetSymbolAddress((void**)&p_cw_h, g_cw_h);

    // 1) prep: conversions + transposes + bias + ln1
    prep_w_kernel<<<NWB + B_OW + B_F2T + 1 + NLN1, 256>>>(
        in_w, m_in_w, m_xp_w, m_out_w, f_w1,
        o_w, o_b, f_w2, f_b2, x, norm_g, norm_b);

    // 2) xp = xs @ in_w^T + in_b
    gemm_bf16_kernel<2, 2><<<dim3(3, 64, 1), 256>>>(p_xs_h, p_w_in, in_b, p_xp_h,
        LROWS, DM, DM, DM, DM, 0, 0, 0, 0, 0, 0, 1);

    // 3) xz[d] = gather_d(xp) @ m_in_w[d]^T
    gemm_bf16_kernel<4, 4><<<dim3(6, 32, 4), 256>>>(p_xp_h, p_w_inproj, nullptr, p_xz_h,
        LROWS, 2 * DI, DM, DM, 2 * DI,
        0, (long)2 * DI * DM, 0, (long)LROWS * 2 * DI, 0, 1, 1);

    // 4) causal depthwise conv + silu
    conv_silu_kernel<<<768, 256>>>(m_conv_w, m_conv_b);

    // 5) dbl[d] = xsm[d] @ m_xp_w[d]^T
    gemm_bf16_kernel<2, 2><<<dim3(1, 64, 4), 256>>>(p_xsm_h, p_w_xp, nullptr, p_dbl,
        LROWS, DBL_W, DI, DI, DBL_W,
        (long)LROWS * DI, (long)DBL_W * DI, 0, (long)LROWS * DBL_W, 0, 0, 0);

    // 6) selective scan
    scan_kernel<<<dim3(6, BATCH, NDIR), 256>>>(m_Alog, m_D, m_dt_w, m_dt_b);

    // 7) fused[:, d*DM:(d+1)*DM] = scatter_d(y[d] @ m_out_w[d]^T)
    gemm_bf16_kernel<4, 2><<<dim3(3, 32, 4), 256>>>(p_y_h, p_w_out, nullptr, p_fused_h,
        LROWS, DM, DI, DI, 4 * DM,
        (long)LROWS * DI, (long)DM * DI, 0, (long)DM, 0, 2, 1);

    // 8) Wc = o_w @ f_w2 (bf16 GEMM)
    gemm_bf16_kernel<2, 2><<<dim3(6, 3, 1), 256>>>(p_w_ow, p_w_f2T, nullptr, p_cw_h,
        DM, 2 * DM, DM, DM, 2 * DM, 0, 0, 0, 0, 0, 0, 1);

    // 9) hdn = gelu(fused @ f_w1^T + f_b1)
    gemm_bf16_kernel<4, 2><<<dim3(6, 32, 1), 256>>>(p_fused_h, p_w_f1, f_b1, p_hdn_h,
        LROWS, 2 * DM, 4 * DM, 4 * DM, 2 * DM, 0, 0, 0, 0, 2, 0, 1);

    // 10) h3 = hdn @ Wc^T + bc
    gemm_bf16_kernel<2, 2><<<dim3(3, 64, 1), 256>>>(p_hdn_h, p_cw_h, p_cb, p_h3,
        LROWS, DM, 2 * DM, 2 * DM, DM, 0, 0, 0, 0, 0, 0, 0);

    // 11) final layernorm + residual + transpose out
    ln2_kernel<<<dim3(64, 4), 256>>>(on_g, on_b, out);
}

// round 16
// speedup vs baseline: 1.0488x; 1.0108x over previous
#include <cuda_runtime.h>
#include <cuda_bf16.h>
#include <math.h>
#include <stdint.h>

// ---------------- problem constants ----------------
#define BATCH 4
#define DM    192
#define DI    384
#define DS    16
#define DR    12
#define NSEQ  1024
#define LROWS 4096
#define NDIR  4
#define DBL_W 44

typedef __nv_bfloat16 bf16;

// ---------------- scratch ----------------
__device__ float g_xs  [LROWS*DM];
__device__ float g_dbl [NDIR*LROWS*DBL_W];
__device__ float g_h3  [LROWS*DM];
__device__ float g_cb  [DM];

__device__ bf16 g_xs_h  [LROWS*DM];
__device__ bf16 g_xp_h  [LROWS*DM];
__device__ bf16 g_xz_h  [(long)NDIR*LROWS*2*DI];
__device__ bf16 g_xsm_h [NDIR*LROWS*DI];
__device__ bf16 g_y_h   [NDIR*LROWS*DI];
__device__ bf16 g_fused_h[LROWS*4*DM];
__device__ bf16 g_hdn_h [LROWS*2*DM];

__device__ bf16 g_w_in_h    [DM*DM];
__device__ bf16 g_w_inproj_h[NDIR*2*DI*DM];
__device__ bf16 g_w_xp_h    [NDIR*DBL_W*DI];
__device__ bf16 g_w_out_h   [NDIR*DM*DI];
__device__ bf16 g_w_f1_h    [2*DM*4*DM];
__device__ bf16 g_w_ow_h    [DM*DM];
__device__ bf16 g_w_f2T     [2*DM*DM];
__device__ bf16 g_cw_h      [DM*2*DM];

// ---------------- helpers ----------------
__device__ __forceinline__ float apply_act(float v, int act) {
    if (act == 1) {
        v = (v > 20.f) ? v : __logf(1.f + __expf(v));
    } else if (act == 2) {
        v = 0.5f * v * (1.f + erff(v * 0.70710678118654752f));
    }
    return v;
}

__device__ __forceinline__ int seq_src_n(int d, int t) {
    if (d == 0) return t;
    if (d == 1) return NSEQ - 1 - t;
    if (d == 2) return ((t & 31) << 5) + (t >> 5);
    int u = NSEQ - 1 - t;
    return ((u & 31) << 5) + (u >> 5);
}

__device__ __forceinline__ void mma_bf16(float4& c,
    uint32_t a0, uint32_t a1, uint32_t a2, uint32_t a3, uint32_t b0, uint32_t b1) {
    asm volatile(
        "mma.sync.aligned.m16n8k16.row.col.f32.bf16.bf16.f32 "
        "{%0,%1,%2,%3}, {%4,%5,%6,%7}, {%8,%9}, {%0,%1,%2,%3};\n"
        : "+f"(c.x), "+f"(c.y), "+f"(c.z), "+f"(c.w)
        : "r"(a0), "r"(a1), "r"(a2), "r"(a3), "r"(b0), "r"(b1));
}

__device__ __forceinline__ void ldsm_x4(uint32_t addr,
    uint32_t& r0, uint32_t& r1, uint32_t& r2, uint32_t& r3) {
    asm volatile("ldmatrix.sync.aligned.m8n8.x4.shared.b16 {%0,%1,%2,%3}, [%4];"
        : "=r"(r0), "=r"(r1), "=r"(r2), "=r"(r3) : "r"(addr));
}

__device__ __forceinline__ uint32_t pack_bf2(float lo, float hi) {
    __nv_bfloat162 p = __floats2bfloat162_rn(lo, hi);
    return *(uint32_t*)&p;
}

__device__ __forceinline__ void cp16(uint32_t saddr, const void* gptr, int src_bytes) {
    asm volatile("cp.async.cg.shared.global [%0], [%1], 16, %2;\n"
        :: "r"(saddr), "l"(gptr), "r"(src_bytes));
}
__device__ __forceinline__ void cp_commit() {
    asm volatile("cp.async.commit_group;\n");
}
__device__ __forceinline__ void cp_wait2() { asm volatile("cp.async.wait_group 2;\n"); }
__device__ __forceinline__ void cp_wait1() { asm volatile("cp.async.wait_group 1;\n"); }
__device__ __forceinline__ void cp_wait0() { asm volatile("cp.async.wait_group 0;\n"); }

// ---------------- prep: vectorized conversions + transpose + bias + ln1 ----------------
#define N_S0 (DM*DM)
#define N_S1 (NDIR*2*DI*DM)
#define N_S2 (NDIR*DBL_W*DI)
#define N_S3 (NDIR*DM*DI)
#define N_S4 (2*DM*4*DM)
#define N_S5 (DM*DM)
#define N_CVT (N_S0+N_S1+N_S2+N_S3+N_S4+N_S5)
#define B_CVT (N_CVT / 8 / 256)                  // 645 (exact)
#define N_F2T (2*DM*DM)
#define B_F2T ((N_F2T + 255) / 256)
#define NLN1 128

__device__ __forceinline__ void cvt8(bf16* dst, const float* src, long i) {
    const float4 a = *(const float4*)(src + i);
    const float4 b = *(const float4*)(src + i + 4);
    uint4 o;
    o.x = pack_bf2(a.x, a.y); o.y = pack_bf2(a.z, a.w);
    o.z = pack_bf2(b.x, b.y); o.w = pack_bf2(b.z, b.w);
    *(uint4*)(dst + i) = o;
}

__global__ __launch_bounds__(256) void prep_w_kernel(
    const float* s0, const float* s1, const float* s2, const float* s3, const float* s4,
    const float* __restrict__ o_w, const float* __restrict__ o_b,
    const float* __restrict__ f_w2, const float* __restrict__ f_b2,
    const float* __restrict__ x, const float* __restrict__ ng, const float* __restrict__ nb)
{
    __shared__ float sh[DM * 33 + 64];
    const int tid = threadIdx.x;
    int blk = blockIdx.x;

    if (blk < B_CVT) {                          // vectorized conversions, 8 elems/thread
        long e = ((long)blk * 256 + tid) * 8;
        if (e < N_S0) { cvt8(g_w_in_h, s0, e); return; }      e -= N_S0;
        if (e < N_S1) { cvt8(g_w_inproj_h, s1, e); return; }  e -= N_S1;
        if (e < N_S2) { cvt8(g_w_xp_h, s2, e); return; }      e -= N_S2;
        if (e < N_S3) { cvt8(g_w_out_h, s3, e); return; }     e -= N_S3;
        if (e < N_S4) { cvt8(g_w_f1_h, s4, e); return; }      e -= N_S4;
        cvt8(g_w_ow_h, o_w, e);
        return;
    }
    blk -= B_CVT;
    if (blk < B_F2T) {                          // f_w2^T: [k][j] = f_w2[j][k]
        long i = (long)blk * 256 + tid;
        if (i < N_F2T) {
            int k = (int)(i / DM), j = (int)(i % DM);
            g_w_f2T[i] = __float2bfloat16(f_w2[j * (2 * DM) + k]);
        }
        return;
    }
    blk -= B_F2T;
    if (blk < 1) {                              // bc = o_w @ f_b2 + o_b
        if (tid < DM) {
            float acc = o_b[tid];
            const float* wr = o_w + (long)tid * DM;
            for (int j = 0; j < DM; j++) acc = fmaf(wr[j], f_b2[j], acc);
            g_cb[tid] = acc;
        }
        return;
    }
    blk -= 1;
    // ---- ln1 blocks ----
    {
        const int idx = blk;                    // 0..127
        const int b = idx >> 5, n0 = (idx & 31) << 5;
        float (*tile)[33] = (float(*)[33])sh;
        __shared__ float s_mean[32], s_rstd[32];

        for (int i = tid; i < DM * 32; i += 256) {
            int d = i >> 5, nn = i & 31;
            tile[d][nn] = x[((long)(b * DM + d) << 10) + n0 + nn];
        }
        __syncthreads();

        const int nn = tid >> 3, l = tid & 7;
        float s = 0.f, s2 = 0.f;
        for (int d = l; d < DM; d += 8) { float v = tile[d][nn]; s += v; s2 = fmaf(v, v, s2); }
        s  += __shfl_down_sync(0xffffffffu, s,  4, 8);
        s2 += __shfl_down_sync(0xffffffffu, s2, 4, 8);
        s  += __shfl_down_sync(0xffffffffu, s,  2, 8);
        s2 += __shfl_down_sync(0xffffffffu, s2, 2, 8);
        s  += __shfl_down_sync(0xffffffffu, s,  1, 8);
        s2 += __shfl_down_sync(0xffffffffu, s2, 1, 8);
        if (l == 0) {
            float m = s * (1.f / DM);
            float var = s2 * (1.f / DM) - m * m;
            s_mean[nn] = m;
            s_rstd[nn] = rsqrtf(var + 1e-5f);
        }
        __syncthreads();

        for (int i = tid; i < DM * 32; i += 256) {
            int nn2 = i / DM, d = i % DM;
            float v = (tile[d][nn2] - s_mean[nn2]) * s_rstd[nn2] * ng[d] + nb[d];
            long adr = ((long)(b << 10) + n0 + nn2) * DM + d;
            g_xs[adr] = v;
            g_xs_h[adr] = __float2bfloat16(v);
        }
    }
}

// ---------------- bf16 cp.async GEMM, BK=32, NST=4, peeled exact tail ----------------
// mode: 0 plain, 1 gather A rows via seq_src_n(z,.), 2 scatter C rows via seq_src_n(z,.)
template<int MFRAG, int NFRAG>
__global__ __launch_bounds__(256) void gemm_bf16_kernel(
    const bf16* __restrict__ A, const bf16* __restrict__ W,
    const float* __restrict__ bias, void* __restrict__ Cv,
    int M, int Nn, int K, int lda, int ldc,
    long sA_, long sW_, long sB_, long sC_, int act, int mode, int cbf)
{
    constexpr int TM = MFRAG * 32;
    constexpr int TN = NFRAG * 32;
    constexpr int PITCH = 40;
    const int z = blockIdx.z;
    A += z * sA_; W += z * sW_;
    const float* bz = bias ? (bias + z * sB_) : (const float*)0;

    __shared__ __align__(16) bf16 sA[4][TM][PITCH];
    __shared__ __align__(16) bf16 sB[4][TN][PITCH];
    constexpr uint32_t A_ST = TM * PITCH * 2;
    constexpr uint32_t B_ST = TN * PITCH * 2;

    const int bm = blockIdx.y * TM, bn = blockIdx.x * TN;
    const int tid = threadIdx.x;

    constexpr int TPR_A = 256 / TM;
    constexpr int NCP_A = 4 / TPR_A;
    constexpr int TPR_B = 256 / TN;
    constexpr int NCP_B = 4 / TPR_B;

    const int rA = tid / TPR_A;
    const int kA = (tid % TPR_A) * (NCP_A * 8);
    long arowi;
    if (mode == 1) {
        int gm = bm + rA;
        arowi = (long)(((gm >> 10) << 10) + seq_src_n(z, gm & 1023));
    } else {
        arowi = bm + rA;
    }
    const bf16* aPtr = A + arowi * lda + kA;
    const int rB = tid / TPR_B;
    const int kB = (tid % TPR_B) * (NCP_B * 8);
    const int gw_n = bn + rB;
    const bool wv = (gw_n < Nn);
    const bf16* wPtr = W + (wv ? (long)gw_n * K : 0) + kB;

    const uint32_t aDst0 = (uint32_t)__cvta_generic_to_shared(&sA[0][rA][kA]);
    const uint32_t bDst0 = (uint32_t)__cvta_generic_to_shared(&sB[0][rB][kB]);

    const int nkt = K >> 5;

    auto issue = [&](int kt) {
        const int s = kt & 3;
#pragma unroll
        for (int q = 0; q < NCP_A; q++)
            cp16(aDst0 + s * A_ST + q * 16, aPtr + (kt << 5) + q * 8, 16);
#pragma unroll
        for (int q = 0; q < NCP_B; q++)
            cp16(bDst0 + s * B_ST + q * 16, wPtr + (kt << 5) + q * 8, wv ? 16 : 0);
        cp_commit();
    };

    issue(0); issue(1); issue(2);

    float4 acc[MFRAG][NFRAG];
#pragma unroll
    for (int i = 0; i < MFRAG; i++)
#pragma unroll
        for (int j = 0; j < NFRAG; j++) acc[i][j] = make_float4(0.f, 0.f, 0.f, 0.f);

    const int lane = tid & 31, wid = tid >> 5;
    const int wm = wid >> 2, wn = wid & 3;

    const int a_row = wm * (MFRAG * 16) + (lane & 7) + (((lane >> 3) & 1) << 3);
    const int a_kc  = (lane >> 4) << 3;
    const uint32_t aAddr0 = (uint32_t)__cvta_generic_to_shared(&sA[0][a_row][a_kc]);
    const int b_row = wn * (NFRAG * 8) + (lane & 7) + ((lane >> 4) << 3);
    const int b_kc  = ((lane >> 3) & 1) << 3;
    const uint32_t bAddr0 = (uint32_t)__cvta_generic_to_shared(&sB[0][b_row][b_kc]);

    auto compute = [&](int kt) {
        const int s = kt & 3;
        const uint32_t aBase = aAddr0 + s * A_ST;
        const uint32_t bBase = bAddr0 + s * B_ST;
#pragma unroll
        for (int s2 = 0; s2 < 2; s2++) {
            const uint32_t aA = aBase + s2 * 32;
            const uint32_t bA = bBase + s2 * 32;
            uint32_t ra[MFRAG][4];
#pragma unroll
            for (int i = 0; i < MFRAG; i++)
                ldsm_x4(aA + i * (16 * PITCH * 2), ra[i][0], ra[i][1], ra[i][2], ra[i][3]);
            uint32_t rb[NFRAG][2];
#pragma unroll
            for (int jp = 0; jp < NFRAG / 2; jp++) {
                uint32_t b0, b1, b2, b3;
                ldsm_x4(bA + jp * (16 * PITCH * 2), b0, b1, b2, b3);
                rb[2 * jp][0] = b0; rb[2 * jp][1] = b1;
                rb[2 * jp + 1][0] = b2; rb[2 * jp + 1][1] = b3;
            }
#pragma unroll
            for (int i = 0; i < MFRAG; i++)
#pragma unroll
                for (int j = 0; j < NFRAG; j++)
                    mma_bf16(acc[i][j], ra[i][0], ra[i][1], ra[i][2], ra[i][3],
                             rb[j][0], rb[j][1]);
        }
    };

    int kt = 0;
    for (; kt < nkt - 3; kt++) {
        cp_wait2();
        __syncthreads();
        issue(kt + 3);
        compute(kt);
    }
    cp_wait2(); __syncthreads(); compute(kt); kt++;
    cp_wait1(); __syncthreads(); compute(kt); kt++;
    cp_wait0(); __syncthreads(); compute(kt);

    // ---- epilogue ----
    const int row0 = lane >> 2;
    const int col0 = (lane & 3) << 1;
    float* Cf = (float*)Cv + z * sC_;
    bf16*  Ch = (bf16*)Cv + z * sC_;
#pragma unroll
    for (int i = 0; i < MFRAG; i++) {
        const int gmA = bm + wm * (MFRAG * 16) + (i << 4) + row0;
        const int gmB = gmA + 8;
        long rAo, rBo;
        if (mode == 2) {
            rAo = ((gmA >> 10) << 10) + seq_src_n(z, gmA & 1023);
            rBo = ((gmB >> 10) << 10) + seq_src_n(z, gmB & 1023);
        } else { rAo = gmA; rBo = gmB; }
#pragma unroll
        for (int j = 0; j < NFRAG; j++) {
            const int gn = bn + wn * (NFRAG * 8) + (j << 3) + col0;
            if (gn < Nn) {
                float4 v = acc[i][j];
                if (bz) {
                    const float b0 = bz[gn], b1 = bz[gn + 1];
                    v.x += b0; v.y += b1; v.z += b0; v.w += b1;
                }
                if (act) {
                    v.x = apply_act(v.x, act); v.y = apply_act(v.y, act);
                    v.z = apply_act(v.z, act); v.w = apply_act(v.w, act);
                }
                if (cbf) {
                    *(uint32_t*)&Ch[rAo * (long)ldc + gn] = pack_bf2(v.x, v.y);
                    *(uint32_t*)&Ch[rBo * (long)ldc + gn] = pack_bf2(v.z, v.w);
                } else {
                    *(float2*)&Cf[rAo * (long)ldc + gn] = make_float2(v.x, v.y);
                    *(float2*)&Cf[rBo * (long)ldc + gn] = make_float2(v.z, v.w);
                }
            }
        }
    }
}

// ---------------- causal depthwise conv + silu, 2 channels per thread ----------------
__global__ __launch_bounds__(256) void conv_silu_kernel(
    const float* __restrict__ cw, const float* __restrict__ cb)
{
    const int gi = blockIdx.x * 256 + threadIdx.x;      // < 16*64*192
    const int cp = gi % 192;
    const int c = cp << 1;
    const int rest = gi / 192;
    const int tb = rest & 63;
    const int db = rest >> 6;
    const int d = db >> 2;
    const int t0 = tb << 4;

    const float* wp = cw + ((long)d * DI + c) * 4;
    const float wa0 = wp[0], wa1 = wp[1], wa2 = wp[2], wa3 = wp[3];
    const float wb0 = wp[4], wb1 = wp[5], wb2 = wp[6], wb3 = wp[7];
    const float ba = cb[d * DI + c];
    const float bb_ = cb[d * DI + c + 1];
    const bf16* src = g_xz_h + ((long)db * NSEQ) * (2 * DI) + c;
    bf16* dst = g_xsm_h + ((long)db * NSEQ) * DI + c;

    auto ld2 = [&](int t) -> float2 {
        __nv_bfloat162 v = *(const __nv_bfloat162*)&src[(long)t * (2 * DI)];
        return make_float2(__bfloat162float(v.x), __bfloat162float(v.y));
    };
    float2 r0 = (t0 >= 3) ? ld2(t0 - 3) : make_float2(0.f, 0.f);
    float2 r1 = (t0 >= 2) ? ld2(t0 - 2) : make_float2(0.f, 0.f);
    float2 r2 = (t0 >= 1) ? ld2(t0 - 1) : make_float2(0.f, 0.f);
#pragma unroll
    for (int i = 0; i < 16; i++) {
        const int t = t0 + i;
        const float2 cur = ld2(t);
        float a = ba;
        a = fmaf(wa0, r0.x, a); a = fmaf(wa1, r1.x, a);
        a = fmaf(wa2, r2.x, a); a = fmaf(wa3, cur.x, a);
        float b = bb_;
        b = fmaf(wb0, r0.y, b); b = fmaf(wb1, r1.y, b);
        b = fmaf(wb2, r2.y, b); b = fmaf(wb3, cur.y, b);
        a = __fdividef(a, 1.f + __expf(-a));
        b = __fdividef(b, 1.f + __expf(-b));
        *(uint32_t*)&dst[(long)t * DI] = pack_bf2(a, b);
        r0 = r1; r1 = r2; r2 = cur;
    }
}

// ---------------- selective scan: fused dt-proj + power-chain dA ----------------
#define SCH 16
__global__ __launch_bounds__(256) void scan_kernel(
    const float* __restrict__ Alog, const float* __restrict__ Dp,
    const float* __restrict__ Wdt, const float* __restrict__ bdt)
{
    const int d = blockIdx.z, b = blockIdx.y;
    const int c0 = blockIdx.x << 6;
    const int tid = threadIdx.x;
    const int cl = tid >> 2;
    const int sg = tid & 3;
    const int c = c0 + cl;
    const long baseI = ((long)d * BATCH + b) * NSEQ;

    const bf16* xb   = g_xsm_h + baseI * DI       + c0;
    const bf16* zb   = g_xz_h  + baseI * (2 * DI) + DI + c0;
    const float* dblp = g_dbl + baseI * DBL_W;
    bf16* yb          = g_y_h + baseI * DI        + c0;

    __shared__ float s_wdt[64 * 13];
    __shared__ float s_bdt[64];
    __shared__ float s_raw[SCH * 12];
    __shared__ float s_bc [SCH * 32];
    __shared__ float s_dt [SCH * 64];
    __shared__ float s_x  [SCH * 64];
    __shared__ float s_g  [SCH * 64];

    for (int i = tid; i < 64 * DR; i += 256)
        s_wdt[(i / DR) * 13 + (i % DR)] = Wdt[((long)(d * DI + c0) + i / DR) * DR + (i % DR)];
    if (tid < 64) s_bdt[tid] = bdt[d * DI + c0 + tid];

    const float LOG2E = 1.44269504088896340736f;
    float Aa[4];
    bool fastf = true;
#pragma unroll
    for (int s = 0; s < 4; s++) {
        const float E = expf(Alog[((long)(d * DI + c)) * DS + (sg << 2) + s]);
        Aa[s] = -E * LOG2E;
        fastf = fastf && (fabsf(E - (float)((sg << 2) + s + 1)) < 1e-3f);
    }
    const float Dv = Dp[d * DI + c];

    float h[4];
#pragma unroll
    for (int s = 0; s < 4; s++) h[s] = 0.f;

    __syncthreads();

    for (int t0 = 0; t0 < NSEQ; t0 += SCH) {
        __syncthreads();
        if (tid < SCH * DR) s_raw[tid] = dblp[(long)(t0 + tid / DR) * DBL_W + (tid % DR)];
#pragma unroll
        for (int k = 0; k < 2; k++) {
            const int idx = tid + (k << 8);
            const int row = idx >> 5, col = idx & 31;
            s_bc[idx] = dblp[(long)(t0 + row) * DBL_W + DR + col];
        }
#pragma unroll
        for (int k = 0; k < 4; k++) {
            const int idx = tid + (k << 8);
            const int row = idx >> 6, col = idx & 63;
            s_x[idx] = __bfloat162float(xb[(long)(t0 + row) * DI + col]);
            const float zv = __bfloat162float(zb[(long)(t0 + row) * (2 * DI) + col]);
            s_g[idx] = __fdividef(zv, 1.f + __expf(-zv));
        }
        __syncthreads();
#pragma unroll
        for (int k = 0; k < 4; k++) {
            const int idx = tid + (k << 8);
            const int row = idx >> 6, col = idx & 63;
            float v = s_bdt[col];
#pragma unroll
            for (int j = 0; j < DR; j++)
                v = fmaf(s_raw[row * DR + j], s_wdt[col * 13 + j], v);
            s_dt[idx] = (v > 20.f) ? v : __logf(1.f + __expf(v));
        }
        __syncthreads();

        if (fastf) {
#pragma unroll
            for (int tt = 0; tt < SCH; tt++) {
                const float dt_v = s_dt[(tt << 6) + cl];
                const float x_v  = s_x [(tt << 6) + cl];
                const float* bc = s_bc + (tt << 5);
                const float dtx = dt_v * x_v;
                const float e1 = exp2f(-LOG2E * dt_v);
                const float e2 = e1 * e1, e3 = e2 * e1, e4 = e2 * e2;
                float eb = 1.f;
                if (sg & 1) eb = e4;
                const float e8 = e4 * e4;
                if (sg & 2) eb *= e8;
                const float dA0 = eb * e1, dA1 = eb * e2, dA2 = eb * e3, dA3 = eb * e4;
                float accv = 0.f;
                h[0] = fmaf(dA0, h[0], dtx * bc[(sg << 2) + 0]);
                accv = fmaf(h[0], bc[16 + (sg << 2) + 0], accv);
                h[1] = fmaf(dA1, h[1], dtx * bc[(sg << 2) + 1]);
                accv = fmaf(h[1], bc[16 + (sg << 2) + 1], accv);
                h[2] = fmaf(dA2, h[2], dtx * bc[(sg << 2) + 2]);
                accv = fmaf(h[2], bc[16 + (sg << 2) + 2], accv);
                h[3] = fmaf(dA3, h[3], dtx * bc[(sg << 2) + 3]);
                accv = fmaf(h[3], bc[16 + (sg << 2) + 3], accv);
                accv += __shfl_down_sync(0xffffffffu, accv, 2, 4);
                accv += __shfl_down_sync(0xffffffffu, accv, 1, 4);
                if (sg == 0) {
                    float yv = fmaf(x_v, Dv, accv);
                    yv *= s_g[(tt << 6) + cl];
                    yb[(long)(t0 + tt) * DI + cl] = __float2bfloat16(yv);
                }
            }
        } else {
#pragma unroll
            for (int tt = 0; tt < SCH; tt++) {
                const float dt_v = s_dt[(tt << 6) + cl];
                const float x_v  = s_x [(tt << 6) + cl];
                const float* bc = s_bc + (tt << 5);
                const float dtx = dt_v * x_v;
                float accv = 0.f;
#pragma unroll
                for (int s = 0; s < 4; s++) {
                    const float dA = exp2f(dt_v * Aa[s]);
                    h[s] = fmaf(dA, h[s], dtx * bc[(sg << 2) + s]);
                    accv = fmaf(h[s], bc[16 + (sg << 2) + s], accv);
                }
                accv += __shfl_down_sync(0xffffffffu, accv, 2, 4);
                accv += __shfl_down_sync(0xffffffffu, accv, 1, 4);
                if (sg == 0) {
                    float yv = fmaf(x_v, Dv, accv);
                    yv *= s_g[(tt << 6) + cl];
                    yb[(long)(t0 + tt) * DI + cl] = __float2bfloat16(yv);
                }
            }
        }
    }
}

// ---------------- final layernorm + residual + transpose-out ----------------
__global__ __launch_bounds__(256) void ln2_kernel(
    const float* __restrict__ g, const float* __restrict__ bb, float* __restrict__ out)
{
    __shared__ float t1[16][193];
    __shared__ float t2[16][193];
    __shared__ float s_mean[16], s_rstd[16];
    const int b = blockIdx.y, n0 = blockIdx.x << 4;
    const int tid = threadIdx.x;

    for (int i = tid; i < 16 * DM; i += 256) {
        int nn = i / DM, dd = i % DM;
        long adr = ((long)(b << 10) + n0 + nn) * DM + dd;
        t1[nn][dd] = g_h3[adr];
        t2[nn][dd] = g_xs[adr];
    }
    __syncthreads();

    const int nn = tid >> 4, l = tid & 15;
    float s = 0.f, s2 = 0.f;
    for (int dd = l; dd < DM; dd += 16) { float v = t1[nn][dd]; s += v; s2 = fmaf(v, v, s2); }
    s  += __shfl_down_sync(0xffffffffu, s,  8, 16);
    s2 += __shfl_down_sync(0xffffffffu, s2, 8, 16);
    s  += __shfl_down_sync(0xffffffffu, s,  4, 16);
    s2 += __shfl_down_sync(0xffffffffu, s2, 4, 16);
    s  += __shfl_down_sync(0xffffffffu, s,  2, 16);
    s2 += __shfl_down_sync(0xffffffffu, s2, 2, 16);
    s  += __shfl_down_sync(0xffffffffu, s,  1, 16);
    s2 += __shfl_down_sync(0xffffffffu, s2, 1, 16);
    if (l == 0) {
        float m = s * (1.f / DM);
        float var = s2 * (1.f / DM) - m * m;
        s_mean[nn] = m;
        s_rstd[nn] = rsqrtf(var + 1e-5f);
    }
    __syncthreads();

    for (int i = tid; i < DM * 16; i += 256) {
        int dd = i >> 4, nn2 = i & 15;
        float v = (t1[nn2][dd] - s_mean[nn2]) * s_rstd[nn2] * g[dd] + bb[dd] + t2[nn2][dd];
        out[((long)(b * DM + dd) << 10) + n0 + nn2] = v;
    }
}

// ---------------- launcher ----------------
extern "C" void kernel_launch(void* const* d_in, const int* in_sizes, int n_in,
                              void* d_out, int out_size)
{
    const float* x        = (const float*)d_in[0];
    const float* norm_g   = (const float*)d_in[1];
    const float* norm_b   = (const float*)d_in[2];
    const float* in_w     = (const float*)d_in[3];
    const float* in_b     = (const float*)d_in[4];
    const float* m_in_w   = (const float*)d_in[5];
    const float* m_conv_w = (const float*)d_in[6];
    const float* m_conv_b = (const float*)d_in[7];
    const float* m_xp_w   = (const float*)d_in[8];
    const float* m_dt_w   = (const float*)d_in[9];
    const float* m_dt_b   = (const float*)d_in[10];
    const float* m_Alog   = (const float*)d_in[11];
    const float* m_D      = (const float*)d_in[12];
    const float* m_out_w  = (const float*)d_in[13];
    const float* f_w1     = (const float*)d_in[14];
    const float* f_b1     = (const float*)d_in[15];
    const float* f_w2     = (const float*)d_in[16];
    const float* f_b2     = (const float*)d_in[17];
    const float* o_w      = (const float*)d_in[18];
    const float* o_b      = (const float*)d_in[19];
    const float* on_g     = (const float*)d_in[20];
    const float* on_b     = (const float*)d_in[21];
    float* out = (float*)d_out;

    float *p_dbl, *p_h3, *p_cb;
    bf16 *p_xs_h, *p_xp_h, *p_xz_h, *p_xsm_h, *p_y_h, *p_fused_h, *p_hdn_h;
    bf16 *p_w_in, *p_w_inproj, *p_w_xp, *p_w_out, *p_w_f1, *p_w_ow, *p_w_f2T, *p_cw_h;
    cudaGetSymbolAddress((void**)&p_dbl, g_dbl);
    cudaGetSymbolAddress((void**)&p_h3, g_h3);
    cudaGetSymbolAddress((void**)&p_cb, g_cb);
    cudaGetSymbolAddress((void**)&p_xs_h, g_xs_h);
    cudaGetSymbolAddress((void**)&p_xp_h, g_xp_h);
    cudaGetSymbolAddress((void**)&p_xz_h, g_xz_h);
    cudaGetSymbolAddress((void**)&p_xsm_h, g_xsm_h);
    cudaGetSymbolAddress((void**)&p_y_h, g_y_h);
    cudaGetSymbolAddress((void**)&p_fused_h, g_fused_h);
    cudaGetSymbolAddress((void**)&p_hdn_h, g_hdn_h);
    cudaGetSymbolAddress((void**)&p_w_in, g_w_in_h);
    cudaGetSymbolAddress((void**)&p_w_inproj, g_w_inproj_h);
    cudaGetSymbolAddress((void**)&p_w_xp, g_w_xp_h);
    cudaGetSymbolAddress((void**)&p_w_out, g_w_out_h);
    cudaGetSymbolAddress((void**)&p_w_f1, g_w_f1_h);
    cudaGetSymbolAddress((void**)&p_w_ow, g_w_ow_h);
    cudaGetSymbolAddress((void**)&p_w_f2T, g_w_f2T);
    cudaGetSymbolAddress((void**)&p_cw_h, g_cw_h);

    // 1) prep: vectorized conversions + transpose + bias + ln1
    prep_w_kernel<<<B_CVT + B_F2T + 1 + NLN1, 256>>>(
        in_w, m_in_w, m_xp_w, m_out_w, f_w1,
        o_w, o_b, f_w2, f_b2, x, norm_g, norm_b);

    // 2) xp = xs @ in_w^T + in_b
    gemm_bf16_kernel<2, 2><<<dim3(3, 64, 1), 256>>>(p_xs_h, p_w_in, in_b, p_xp_h,
        LROWS, DM, DM, DM, DM, 0, 0, 0, 0, 0, 0, 1);

    // 3) xz[d] = gather_d(xp) @ m_in_w[d]^T
    gemm_bf16_kernel<4, 4><<<dim3(6, 32, 4), 256>>>(p_xp_h, p_w_inproj, nullptr, p_xz_h,
        LROWS, 2 * DI, DM, DM, 2 * DI,
        0, (long)2 * DI * DM, 0, (long)LROWS * 2 * DI, 0, 1, 1);

    // 4) causal depthwise conv + silu
    conv_silu_kernel<<<768, 256>>>(m_conv_w, m_conv_b);

    // 5) dbl[d] = xsm[d] @ m_xp_w[d]^T
    gemm_bf16_kernel<2, 2><<<dim3(1, 64, 4), 256>>>(p_xsm_h, p_w_xp, nullptr, p_dbl,
        LROWS, DBL_W, DI, DI, DBL_W,
        (long)LROWS * DI, (long)DBL_W * DI, 0, (long)LROWS * DBL_W, 0, 0, 0);

    // 6) selective scan
    scan_kernel<<<dim3(6, BATCH, NDIR), 256>>>(m_Alog, m_D, m_dt_w, m_dt_b);

    // 7) fused[:, d*DM:(d+1)*DM] = scatter_d(y[d] @ m_out_w[d]^T)
    gemm_bf16_kernel<4, 2><<<dim3(3, 32, 4), 256>>>(p_y_h, p_w_out, nullptr, p_fused_h,
        LROWS, DM, DI, DI, 4 * DM,
        (long)LROWS * DI, (long)DM * DI, 0, (long)DM, 0, 2, 1);

    // 8) Wc = o_w @ f_w2 (bf16 GEMM)
    gemm_bf16_kernel<2, 2><<<dim3(6, 3, 1), 256>>>(p_w_ow, p_w_f2T, nullptr, p_cw_h,
        DM, 2 * DM, DM, DM, 2 * DM, 0, 0, 0, 0, 0, 0, 1);

    // 9) hdn = gelu(fused @ f_w1^T + f_b1)
    gemm_bf16_kernel<4, 2><<<dim3(6, 32, 1), 256>>>(p_fused_h, p_w_f1, f_b1, p_hdn_h,
        LROWS, 2 * DM, 4 * DM, 4 * DM, 2 * DM, 0, 0, 0, 0, 2, 0, 1);

    // 10) h3 = hdn @ Wc^T + bc
    gemm_bf16_kernel<2, 2><<<dim3(3, 64, 1), 256>>>(p_hdn_h, p_cw_h, p_cb, p_h3,
        LROWS, DM, 2 * DM, 2 * DM, DM, 0, 0, 0, 0, 0, 0, 0);

    // 11) final layernorm + residual + transpose out
    ln2_kernel<<<dim3(64, 4), 256>>>(on_g, on_b, out);
}

// round 17
// speedup vs baseline: 1.0794x; 1.0291x over previous
#include <cuda_runtime.h>
#include <cuda_bf16.h>
#include <math.h>
#include <stdint.h>

// ---------------- problem constants ----------------
#define BATCH 4
#define DM    192
#define DI    384
#define DS    16
#define DR    12
#define NSEQ  1024
#define LROWS 4096
#define NDIR  4
#define DBL_W 44

typedef __nv_bfloat16 bf16;

// ---------------- scratch ----------------
__device__ float g_xs  [LROWS*DM];
__device__ float g_dbl [NDIR*LROWS*DBL_W];
__device__ float g_h3  [LROWS*DM];
__device__ float g_cb  [DM];

__device__ bf16 g_xs_h  [LROWS*DM];
__device__ bf16 g_xp_h  [LROWS*DM];
__device__ bf16 g_xz_h  [(long)NDIR*LROWS*2*DI];
__device__ bf16 g_xsm_h [NDIR*LROWS*DI];
__device__ bf16 g_y_h   [NDIR*LROWS*DI];
__device__ bf16 g_fused_h[LROWS*4*DM];
__device__ bf16 g_hdn_h [LROWS*2*DM];

__device__ bf16 g_w_in_h    [DM*DM];
__device__ bf16 g_w_inproj_h[NDIR*2*DI*DM];
__device__ bf16 g_w_xp_h    [NDIR*DBL_W*DI];
__device__ bf16 g_w_out_h   [NDIR*DM*DI];
__device__ bf16 g_w_f1_h    [2*DM*4*DM];
__device__ bf16 g_w_ow_h    [DM*DM];
__device__ bf16 g_w_f2T     [2*DM*DM];
__device__ bf16 g_cw_h      [DM*2*DM];

// ---------------- helpers ----------------
__device__ __forceinline__ float apply_act(float v, int act) {
    if (act == 1) {
        v = (v > 20.f) ? v : __logf(1.f + __expf(v));
    } else if (act == 2) {
        v = 0.5f * v * (1.f + erff(v * 0.70710678118654752f));
    }
    return v;
}

__device__ __forceinline__ int seq_src_n(int d, int t) {
    if (d == 0) return t;
    if (d == 1) return NSEQ - 1 - t;
    if (d == 2) return ((t & 31) << 5) + (t >> 5);
    int u = NSEQ - 1 - t;
    return ((u & 31) << 5) + (u >> 5);
}

__device__ __forceinline__ void mma_bf16(float4& c,
    uint32_t a0, uint32_t a1, uint32_t a2, uint32_t a3, uint32_t b0, uint32_t b1) {
    asm volatile(
        "mma.sync.aligned.m16n8k16.row.col.f32.bf16.bf16.f32 "
        "{%0,%1,%2,%3}, {%4,%5,%6,%7}, {%8,%9}, {%0,%1,%2,%3};\n"
        : "+f"(c.x), "+f"(c.y), "+f"(c.z), "+f"(c.w)
        : "r"(a0), "r"(a1), "r"(a2), "r"(a3), "r"(b0), "r"(b1));
}

__device__ __forceinline__ void ldsm_x4(uint32_t addr,
    uint32_t& r0, uint32_t& r1, uint32_t& r2, uint32_t& r3) {
    asm volatile("ldmatrix.sync.aligned.m8n8.x4.shared.b16 {%0,%1,%2,%3}, [%4];"
        : "=r"(r0), "=r"(r1), "=r"(r2), "=r"(r3) : "r"(addr));
}

__device__ __forceinline__ uint32_t pack_bf2(float lo, float hi) {
    __nv_bfloat162 p = __floats2bfloat162_rn(lo, hi);
    return *(uint32_t*)&p;
}

__device__ __forceinline__ void cp16(uint32_t saddr, const void* gptr, int src_bytes) {
    asm volatile("cp.async.cg.shared.global [%0], [%1], 16, %2;\n"
        :: "r"(saddr), "l"(gptr), "r"(src_bytes));
}
__device__ __forceinline__ void cp_commit() {
    asm volatile("cp.async.commit_group;\n");
}
__device__ __forceinline__ void cp_wait2() { asm volatile("cp.async.wait_group 2;\n"); }
__device__ __forceinline__ void cp_wait1() { asm volatile("cp.async.wait_group 1;\n"); }
__device__ __forceinline__ void cp_wait0() { asm volatile("cp.async.wait_group 0;\n"); }

// ---------------- prep: vectorized conversions + transpose + bias + ln1 ----------------
#define N_S0 (DM*DM)
#define N_S1 (NDIR*2*DI*DM)
#define N_S2 (NDIR*DBL_W*DI)
#define N_S3 (NDIR*DM*DI)
#define N_S4 (2*DM*4*DM)
#define N_S5 (DM*DM)
#define N_CVT (N_S0+N_S1+N_S2+N_S3+N_S4+N_S5)
#define B_CVT (N_CVT / 8 / 256)
#define N_F2T (2*DM*DM)
#define B_F2T ((N_F2T + 255) / 256)
#define NLN1 128

__device__ __forceinline__ void cvt8(bf16* dst, const float* src, long i) {
    const float4 a = *(const float4*)(src + i);
    const float4 b = *(const float4*)(src + i + 4);
    uint4 o;
    o.x = pack_bf2(a.x, a.y); o.y = pack_bf2(a.z, a.w);
    o.z = pack_bf2(b.x, b.y); o.w = pack_bf2(b.z, b.w);
    *(uint4*)(dst + i) = o;
}

__global__ __launch_bounds__(256) void prep_w_kernel(
    const float* s0, const float* s1, const float* s2, const float* s3, const float* s4,
    const float* __restrict__ o_w, const float* __restrict__ o_b,
    const float* __restrict__ f_w2, const float* __restrict__ f_b2,
    const float* __restrict__ x, const float* __restrict__ ng, const float* __restrict__ nb)
{
    __shared__ float sh[DM * 33 + 64];
    const int tid = threadIdx.x;
    int blk = blockIdx.x;

    if (blk < B_CVT) {
        long e = ((long)blk * 256 + tid) * 8;
        if (e < N_S0) { cvt8(g_w_in_h, s0, e); return; }      e -= N_S0;
        if (e < N_S1) { cvt8(g_w_inproj_h, s1, e); return; }  e -= N_S1;
        if (e < N_S2) { cvt8(g_w_xp_h, s2, e); return; }      e -= N_S2;
        if (e < N_S3) { cvt8(g_w_out_h, s3, e); return; }     e -= N_S3;
        if (e < N_S4) { cvt8(g_w_f1_h, s4, e); return; }      e -= N_S4;
        cvt8(g_w_ow_h, o_w, e);
        return;
    }
    blk -= B_CVT;
    if (blk < B_F2T) {
        long i = (long)blk * 256 + tid;
        if (i < N_F2T) {
            int k = (int)(i / DM), j = (int)(i % DM);
            g_w_f2T[i] = __float2bfloat16(f_w2[j * (2 * DM) + k]);
        }
        return;
    }
    blk -= B_F2T;
    if (blk < 1) {
        if (tid < DM) {
            float acc = o_b[tid];
            const float* wr = o_w + (long)tid * DM;
            for (int j = 0; j < DM; j++) acc = fmaf(wr[j], f_b2[j], acc);
            g_cb[tid] = acc;
        }
        return;
    }
    blk -= 1;
    {
        const int idx = blk;
        const int b = idx >> 5, n0 = (idx & 31) << 5;
        float (*tile)[33] = (float(*)[33])sh;
        __shared__ float s_mean[32], s_rstd[32];

        for (int i = tid; i < DM * 32; i += 256) {
            int d = i >> 5, nn = i & 31;
            tile[d][nn] = x[((long)(b * DM + d) << 10) + n0 + nn];
        }
        __syncthreads();

        const int nn = tid >> 3, l = tid & 7;
        float s = 0.f, s2 = 0.f;
        for (int d = l; d < DM; d += 8) { float v = tile[d][nn]; s += v; s2 = fmaf(v, v, s2); }
        s  += __shfl_down_sync(0xffffffffu, s,  4, 8);
        s2 += __shfl_down_sync(0xffffffffu, s2, 4, 8);
        s  += __shfl_down_sync(0xffffffffu, s,  2, 8);
        s2 += __shfl_down_sync(0xffffffffu, s2, 2, 8);
        s  += __shfl_down_sync(0xffffffffu, s,  1, 8);
        s2 += __shfl_down_sync(0xffffffffu, s2, 1, 8);
        if (l == 0) {
            float m = s * (1.f / DM);
            float var = s2 * (1.f / DM) - m * m;
            s_mean[nn] = m;
            s_rstd[nn] = rsqrtf(var + 1e-5f);
        }
        __syncthreads();

        for (int i = tid; i < DM * 32; i += 256) {
            int nn2 = i / DM, d = i % DM;
            float v = (tile[d][nn2] - s_mean[nn2]) * s_rstd[nn2] * ng[d] + nb[d];
            long adr = ((long)(b << 10) + n0 + nn2) * DM + d;
            g_xs[adr] = v;
            g_xs_h[adr] = __float2bfloat16(v);
        }
    }
}

// ---------------- bf16 cp.async GEMM, BK=32, NST=4, peeled exact tail ----------------
template<int MFRAG, int NFRAG>
__global__ __launch_bounds__(256) void gemm_bf16_kernel(
    const bf16* __restrict__ A, const bf16* __restrict__ W,
    const float* __restrict__ bias, void* __restrict__ Cv,
    int M, int Nn, int K, int lda, int ldc,
    long sA_, long sW_, long sB_, long sC_, int act, int mode, int cbf)
{
    constexpr int TM = MFRAG * 32;
    constexpr int TN = NFRAG * 32;
    constexpr int PITCH = 40;
    const int z = blockIdx.z;
    A += z * sA_; W += z * sW_;
    const float* bz = bias ? (bias + z * sB_) : (const float*)0;

    __shared__ __align__(16) bf16 sA[4][TM][PITCH];
    __shared__ __align__(16) bf16 sB[4][TN][PITCH];
    constexpr uint32_t A_ST = TM * PITCH * 2;
    constexpr uint32_t B_ST = TN * PITCH * 2;

    const int bm = blockIdx.y * TM, bn = blockIdx.x * TN;
    const int tid = threadIdx.x;

    constexpr int TPR_A = 256 / TM;
    constexpr int NCP_A = 4 / TPR_A;
    constexpr int TPR_B = 256 / TN;
    constexpr int NCP_B = 4 / TPR_B;

    const int rA = tid / TPR_A;
    const int kA = (tid % TPR_A) * (NCP_A * 8);
    long arowi;
    if (mode == 1) {
        int gm = bm + rA;
        arowi = (long)(((gm >> 10) << 10) + seq_src_n(z, gm & 1023));
    } else {
        arowi = bm + rA;
    }
    const bf16* aPtr = A + arowi * lda + kA;
    const int rB = tid / TPR_B;
    const int kB = (tid % TPR_B) * (NCP_B * 8);
    const int gw_n = bn + rB;
    const bool wv = (gw_n < Nn);
    const bf16* wPtr = W + (wv ? (long)gw_n * K : 0) + kB;

    const uint32_t aDst0 = (uint32_t)__cvta_generic_to_shared(&sA[0][rA][kA]);
    const uint32_t bDst0 = (uint32_t)__cvta_generic_to_shared(&sB[0][rB][kB]);

    const int nkt = K >> 5;

    auto issue = [&](int kt) {
        const int s = kt & 3;
#pragma unroll
        for (int q = 0; q < NCP_A; q++)
            cp16(aDst0 + s * A_ST + q * 16, aPtr + (kt << 5) + q * 8, 16);
#pragma unroll
        for (int q = 0; q < NCP_B; q++)
            cp16(bDst0 + s * B_ST + q * 16, wPtr + (kt << 5) + q * 8, wv ? 16 : 0);
        cp_commit();
    };

    issue(0); issue(1); issue(2);

    float4 acc[MFRAG][NFRAG];
#pragma unroll
    for (int i = 0; i < MFRAG; i++)
#pragma unroll
        for (int j = 0; j < NFRAG; j++) acc[i][j] = make_float4(0.f, 0.f, 0.f, 0.f);

    const int lane = tid & 31, wid = tid >> 5;
    const int wm = wid >> 2, wn = wid & 3;

    const int a_row = wm * (MFRAG * 16) + (lane & 7) + (((lane >> 3) & 1) << 3);
    const int a_kc  = (lane >> 4) << 3;
    const uint32_t aAddr0 = (uint32_t)__cvta_generic_to_shared(&sA[0][a_row][a_kc]);
    const int b_row = wn * (NFRAG * 8) + (lane & 7) + ((lane >> 4) << 3);
    const int b_kc  = ((lane >> 3) & 1) << 3;
    const uint32_t bAddr0 = (uint32_t)__cvta_generic_to_shared(&sB[0][b_row][b_kc]);

    auto compute = [&](int kt) {
        const int s = kt & 3;
        const uint32_t aBase = aAddr0 + s * A_ST;
        const uint32_t bBase = bAddr0 + s * B_ST;
#pragma unroll
        for (int s2 = 0; s2 < 2; s2++) {
            const uint32_t aA = aBase + s2 * 32;
            const uint32_t bA = bBase + s2 * 32;
            uint32_t ra[MFRAG][4];
#pragma unroll
            for (int i = 0; i < MFRAG; i++)
                ldsm_x4(aA + i * (16 * PITCH * 2), ra[i][0], ra[i][1], ra[i][2], ra[i][3]);
            uint32_t rb[NFRAG][2];
#pragma unroll
            for (int jp = 0; jp < NFRAG / 2; jp++) {
                uint32_t b0, b1, b2, b3;
                ldsm_x4(bA + jp * (16 * PITCH * 2), b0, b1, b2, b3);
                rb[2 * jp][0] = b0; rb[2 * jp][1] = b1;
                rb[2 * jp + 1][0] = b2; rb[2 * jp + 1][1] = b3;
            }
#pragma unroll
            for (int i = 0; i < MFRAG; i++)
#pragma unroll
                for (int j = 0; j < NFRAG; j++)
                    mma_bf16(acc[i][j], ra[i][0], ra[i][1], ra[i][2], ra[i][3],
                             rb[j][0], rb[j][1]);
        }
    };

    int kt = 0;
    for (; kt < nkt - 3; kt++) {
        cp_wait2();
        __syncthreads();
        issue(kt + 3);
        compute(kt);
    }
    cp_wait2(); __syncthreads(); compute(kt); kt++;
    cp_wait1(); __syncthreads(); compute(kt); kt++;
    cp_wait0(); __syncthreads(); compute(kt);

    // ---- epilogue ----
    const int row0 = lane >> 2;
    const int col0 = (lane & 3) << 1;
    float* Cf = (float*)Cv + z * sC_;
    bf16*  Ch = (bf16*)Cv + z * sC_;
#pragma unroll
    for (int i = 0; i < MFRAG; i++) {
        const int gmA = bm + wm * (MFRAG * 16) + (i << 4) + row0;
        const int gmB = gmA + 8;
        long rAo, rBo;
        if (mode == 2) {
            rAo = ((gmA >> 10) << 10) + seq_src_n(z, gmA & 1023);
            rBo = ((gmB >> 10) << 10) + seq_src_n(z, gmB & 1023);
        } else { rAo = gmA; rBo = gmB; }
#pragma unroll
        for (int j = 0; j < NFRAG; j++) {
            const int gn = bn + wn * (NFRAG * 8) + (j << 3) + col0;
            if (gn < Nn) {
                float4 v = acc[i][j];
                if (bz) {
                    const float b0 = bz[gn], b1 = bz[gn + 1];
                    v.x += b0; v.y += b1; v.z += b0; v.w += b1;
                }
                if (act) {
                    v.x = apply_act(v.x, act); v.y = apply_act(v.y, act);
                    v.z = apply_act(v.z, act); v.w = apply_act(v.w, act);
                }
                if (cbf) {
                    *(uint32_t*)&Ch[rAo * (long)ldc + gn] = pack_bf2(v.x, v.y);
                    *(uint32_t*)&Ch[rBo * (long)ldc + gn] = pack_bf2(v.z, v.w);
                } else {
                    *(float2*)&Cf[rAo * (long)ldc + gn] = make_float2(v.x, v.y);
                    *(float2*)&Cf[rBo * (long)ldc + gn] = make_float2(v.z, v.w);
                }
            }
        }
    }
}

// ---------------- causal depthwise conv + silu, 2 channels per thread ----------------
__global__ __launch_bounds__(256) void conv_silu_kernel(
    const float* __restrict__ cw, const float* __restrict__ cb)
{
    const int gi = blockIdx.x * 256 + threadIdx.x;
    const int cp = gi % 192;
    const int c = cp << 1;
    const int rest = gi / 192;
    const int tb = rest & 63;
    const int db = rest >> 6;
    const int d = db >> 2;
    const int t0 = tb << 4;

    const float* wp = cw + ((long)d * DI + c) * 4;
    const float wa0 = wp[0], wa1 = wp[1], wa2 = wp[2], wa3 = wp[3];
    const float wb0 = wp[4], wb1 = wp[5], wb2 = wp[6], wb3 = wp[7];
    const float ba = cb[d * DI + c];
    const float bb_ = cb[d * DI + c + 1];
    const bf16* src = g_xz_h + ((long)db * NSEQ) * (2 * DI) + c;
    bf16* dst = g_xsm_h + ((long)db * NSEQ) * DI + c;

    auto ld2 = [&](int t) -> float2 {
        __nv_bfloat162 v = *(const __nv_bfloat162*)&src[(long)t * (2 * DI)];
        return make_float2(__bfloat162float(v.x), __bfloat162float(v.y));
    };
    float2 r0 = (t0 >= 3) ? ld2(t0 - 3) : make_float2(0.f, 0.f);
    float2 r1 = (t0 >= 2) ? ld2(t0 - 2) : make_float2(0.f, 0.f);
    float2 r2 = (t0 >= 1) ? ld2(t0 - 1) : make_float2(0.f, 0.f);
#pragma unroll
    for (int i = 0; i < 16; i++) {
        const int t = t0 + i;
        const float2 cur = ld2(t);
        float a = ba;
        a = fmaf(wa0, r0.x, a); a = fmaf(wa1, r1.x, a);
        a = fmaf(wa2, r2.x, a); a = fmaf(wa3, cur.x, a);
        float b = bb_;
        b = fmaf(wb0, r0.y, b); b = fmaf(wb1, r1.y, b);
        b = fmaf(wb2, r2.y, b); b = fmaf(wb3, cur.y, b);
        a = __fdividef(a, 1.f + __expf(-a));
        b = __fdividef(b, 1.f + __expf(-b));
        *(uint32_t*)&dst[(long)t * DI] = pack_bf2(a, b);
        r0 = r1; r1 = r2; r2 = cur;
    }
}

// ---------------- selective scan: fused dt-proj, vectorized smem reads ----------------
#define SCH 16
__global__ __launch_bounds__(256) void scan_kernel(
    const float* __restrict__ Alog, const float* __restrict__ Dp,
    const float* __restrict__ Wdt, const float* __restrict__ bdt)
{
    const int d = blockIdx.z, b = blockIdx.y;
    const int c0 = blockIdx.x << 6;
    const int tid = threadIdx.x;
    const int cl = tid >> 2;
    const int sg = tid & 3;
    const int c = c0 + cl;
    const long baseI = ((long)d * BATCH + b) * NSEQ;

    const bf16* xb   = g_xsm_h + baseI * DI       + c0;
    const bf16* zb   = g_xz_h  + baseI * (2 * DI) + DI + c0;
    const float* dblp = g_dbl + baseI * DBL_W;
    bf16* yb          = g_y_h + baseI * DI        + c0;

    __shared__ float  s_wdt[64 * 13];
    __shared__ float  s_bdt[64];
    __shared__ float  s_raw[SCH * 12];
    __shared__ __align__(16) float s_bc[SCH * 32];
    __shared__ float  s_dt[SCH * 64];
    __shared__ __align__(8) float2 s_xg[SCH * 64];   // packed (x, silu(z))

    for (int i = tid; i < 64 * DR; i += 256)
        s_wdt[(i / DR) * 13 + (i % DR)] = Wdt[((long)(d * DI + c0) + i / DR) * DR + (i % DR)];
    if (tid < 64) s_bdt[tid] = bdt[d * DI + c0 + tid];

    const float LOG2E = 1.44269504088896340736f;
    float Aa[4];
    bool fastf = true;
#pragma unroll
    for (int s = 0; s < 4; s++) {
        const float E = expf(Alog[((long)(d * DI + c)) * DS + (sg << 2) + s]);
        Aa[s] = -E * LOG2E;
        fastf = fastf && (fabsf(E - (float)((sg << 2) + s + 1)) < 1e-3f);
    }
    const float Dv = Dp[d * DI + c];

    float h[4];
#pragma unroll
    for (int s = 0; s < 4; s++) h[s] = 0.f;

    __syncthreads();

    for (int t0 = 0; t0 < NSEQ; t0 += SCH) {
        __syncthreads();
        if (tid < SCH * DR) s_raw[tid] = dblp[(long)(t0 + tid / DR) * DBL_W + (tid % DR)];
#pragma unroll
        for (int k = 0; k < 2; k++) {
            const int idx = tid + (k << 8);
            const int row = idx >> 5, col = idx & 31;
            s_bc[idx] = dblp[(long)(t0 + row) * DBL_W + DR + col];
        }
#pragma unroll
        for (int k = 0; k < 4; k++) {
            const int idx = tid + (k << 8);
            const int row = idx >> 6, col = idx & 63;
            const float xv = __bfloat162float(xb[(long)(t0 + row) * DI + col]);
            const float zv = __bfloat162float(zb[(long)(t0 + row) * (2 * DI) + col]);
            s_xg[idx] = make_float2(xv, __fdividef(zv, 1.f + __expf(-zv)));
        }
        __syncthreads();
#pragma unroll
        for (int k = 0; k < 4; k++) {
            const int idx = tid + (k << 8);
            const int row = idx >> 6, col = idx & 63;
            float v = s_bdt[col];
#pragma unroll
            for (int j = 0; j < DR; j++)
                v = fmaf(s_raw[row * DR + j], s_wdt[col * 13 + j], v);
            s_dt[idx] = (v > 20.f) ? v : __logf(1.f + __expf(v));
        }
        __syncthreads();

        if (fastf) {
#pragma unroll
            for (int tt = 0; tt < SCH; tt++) {
                const float dt_v = s_dt[(tt << 6) + cl];
                const float2 xg  = s_xg[(tt << 6) + cl];
                const float4 bcB = *(const float4*)(s_bc + (tt << 5) + (sg << 2));
                const float4 bcC = *(const float4*)(s_bc + (tt << 5) + 16 + (sg << 2));
                const float dtx = dt_v * xg.x;
                const float e1 = exp2f(-LOG2E * dt_v);
                const float e2 = e1 * e1, e3 = e2 * e1, e4 = e2 * e2;
                float eb = 1.f;
                if (sg & 1) eb = e4;
                const float e8 = e4 * e4;
                if (sg & 2) eb *= e8;
                const float dA0 = eb * e1, dA1 = eb * e2, dA2 = eb * e3, dA3 = eb * e4;
                float accv = 0.f;
                h[0] = fmaf(dA0, h[0], dtx * bcB.x);
                accv = fmaf(h[0], bcC.x, accv);
                h[1] = fmaf(dA1, h[1], dtx * bcB.y);
                accv = fmaf(h[1], bcC.y, accv);
                h[2] = fmaf(dA2, h[2], dtx * bcB.z);
                accv = fmaf(h[2], bcC.z, accv);
                h[3] = fmaf(dA3, h[3], dtx * bcB.w);
                accv = fmaf(h[3], bcC.w, accv);
                accv += __shfl_down_sync(0xffffffffu, accv, 2, 4);
                accv += __shfl_down_sync(0xffffffffu, accv, 1, 4);
                if (sg == 0) {
                    float yv = fmaf(xg.x, Dv, accv);
                    yv *= xg.y;
                    yb[(long)(t0 + tt) * DI + cl] = __float2bfloat16(yv);
                }
            }
        } else {
#pragma unroll
            for (int tt = 0; tt < SCH; tt++) {
                const float dt_v = s_dt[(tt << 6) + cl];
                const float2 xg  = s_xg[(tt << 6) + cl];
                const float4 bcB = *(const float4*)(s_bc + (tt << 5) + (sg << 2));
                const float4 bcC = *(const float4*)(s_bc + (tt << 5) + 16 + (sg << 2));
                const float dtx = dt_v * xg.x;
                float accv = 0.f;
                {
                    const float dA = exp2f(dt_v * Aa[0]);
                    h[0] = fmaf(dA, h[0], dtx * bcB.x);
                    accv = fmaf(h[0], bcC.x, accv);
                }
                {
                    const float dA = exp2f(dt_v * Aa[1]);
                    h[1] = fmaf(dA, h[1], dtx * bcB.y);
                    accv = fmaf(h[1], bcC.y, accv);
                }
                {
                    const float dA = exp2f(dt_v * Aa[2]);
                    h[2] = fmaf(dA, h[2], dtx * bcB.z);
                    accv = fmaf(h[2], bcC.z, accv);
                }
                {
                    const float dA = exp2f(dt_v * Aa[3]);
                    h[3] = fmaf(dA, h[3], dtx * bcB.w);
                    accv = fmaf(h[3], bcC.w, accv);
                }
                accv += __shfl_down_sync(0xffffffffu, accv, 2, 4);
                accv += __shfl_down_sync(0xffffffffu, accv, 1, 4);
                if (sg == 0) {
                    float yv = fmaf(xg.x, Dv, accv);
                    yv *= xg.y;
                    yb[(long)(t0 + tt) * DI + cl] = __float2bfloat16(yv);
                }
            }
        }
    }
}

// ---------------- final layernorm + residual + transpose-out ----------------
__global__ __launch_bounds__(256) void ln2_kernel(
    const float* __restrict__ g, const float* __restrict__ bb, float* __restrict__ out)
{
    __shared__ float t1[16][193];
    __shared__ float t2[16][193];
    __shared__ float s_mean[16], s_rstd[16];
    const int b = blockIdx.y, n0 = blockIdx.x << 4;
    const int tid = threadIdx.x;

    for (int i = tid; i < 16 * DM; i += 256) {
        int nn = i / DM, dd = i % DM;
        long adr = ((long)(b << 10) + n0 + nn) * DM + dd;
        t1[nn][dd] = g_h3[adr];
        t2[nn][dd] = g_xs[adr];
    }
    __syncthreads();

    const int nn = tid >> 4, l = tid & 15;
    float s = 0.f, s2 = 0.f;
    for (int dd = l; dd < DM; dd += 16) { float v = t1[nn][dd]; s += v; s2 = fmaf(v, v, s2); }
    s  += __shfl_down_sync(0xffffffffu, s,  8, 16);
    s2 += __shfl_down_sync(0xffffffffu, s2, 8, 16);
    s  += __shfl_down_sync(0xffffffffu, s,  4, 16);
    s2 += __shfl_down_sync(0xffffffffu, s2, 4, 16);
    s  += __shfl_down_sync(0xffffffffu, s,  2, 16);
    s2 += __shfl_down_sync(0xffffffffu, s2, 2, 16);
    s  += __shfl_down_sync(0xffffffffu, s,  1, 16);
    s2 += __shfl_down_sync(0xffffffffu, s2, 1, 16);
    if (l == 0) {
        float m = s * (1.f / DM);
        float var = s2 * (1.f / DM) - m * m;
        s_mean[nn] = m;
        s_rstd[nn] = rsqrtf(var + 1e-5f);
    }
    __syncthreads();

    for (int i = tid; i < DM * 16; i += 256) {
        int dd = i >> 4, nn2 = i & 15;
        float v = (t1[nn2][dd] - s_mean[nn2]) * s_rstd[nn2] * g[dd] + bb[dd] + t2[nn2][dd];
        out[((long)(b * DM + dd) << 10) + n0 + nn2] = v;
    }
}

// ---------------- launcher ----------------
extern "C" void kernel_launch(void* const* d_in, const int* in_sizes, int n_in,
                              void* d_out, int out_size)
{
    const float* x        = (const float*)d_in[0];
    const float* norm_g   = (const float*)d_in[1];
    const float* norm_b   = (const float*)d_in[2];
    const float* in_w     = (const float*)d_in[3];
    const float* in_b     = (const float*)d_in[4];
    const float* m_in_w   = (const float*)d_in[5];
    const float* m_conv_w = (const float*)d_in[6];
    const float* m_conv_b = (const float*)d_in[7];
    const float* m_xp_w   = (const float*)d_in[8];
    const float* m_dt_w   = (const float*)d_in[9];
    const float* m_dt_b   = (const float*)d_in[10];
    const float* m_Alog   = (const float*)d_in[11];
    const float* m_D      = (const float*)d_in[12];
    const float* m_out_w  = (const float*)d_in[13];
    const float* f_w1     = (const float*)d_in[14];
    const float* f_b1     = (const float*)d_in[15];
    const float* f_w2     = (const float*)d_in[16];
    const float* f_b2     = (const float*)d_in[17];
    const float* o_w      = (const float*)d_in[18];
    const float* o_b      = (const float*)d_in[19];
    const float* on_g     = (const float*)d_in[20];
    const float* on_b     = (const float*)d_in[21];
    float* out = (float*)d_out;

    float *p_dbl, *p_h3, *p_cb;
    bf16 *p_xs_h, *p_xp_h, *p_xz_h, *p_xsm_h, *p_y_h, *p_fused_h, *p_hdn_h;
    bf16 *p_w_in, *p_w_inproj, *p_w_xp, *p_w_out, *p_w_f1, *p_w_ow, *p_w_f2T, *p_cw_h;
    cudaGetSymbolAddress((void**)&p_dbl, g_dbl);
    cudaGetSymbolAddress((void**)&p_h3, g_h3);
    cudaGetSymbolAddress((void**)&p_cb, g_cb);
    cudaGetSymbolAddress((void**)&p_xs_h, g_xs_h);
    cudaGetSymbolAddress((void**)&p_xp_h, g_xp_h);
    cudaGetSymbolAddress((void**)&p_xz_h, g_xz_h);
    cudaGetSymbolAddress((void**)&p_xsm_h, g_xsm_h);
    cudaGetSymbolAddress((void**)&p_y_h, g_y_h);
    cudaGetSymbolAddress((void**)&p_fused_h, g_fused_h);
    cudaGetSymbolAddress((void**)&p_hdn_h, g_hdn_h);
    cudaGetSymbolAddress((void**)&p_w_in, g_w_in_h);
    cudaGetSymbolAddress((void**)&p_w_inproj, g_w_inproj_h);
    cudaGetSymbolAddress((void**)&p_w_xp, g_w_xp_h);
    cudaGetSymbolAddress((void**)&p_w_out, g_w_out_h);
    cudaGetSymbolAddress((void**)&p_w_f1, g_w_f1_h);
    cudaGetSymbolAddress((void**)&p_w_ow, g_w_ow_h);
    cudaGetSymbolAddress((void**)&p_w_f2T, g_w_f2T);
    cudaGetSymbolAddress((void**)&p_cw_h, g_cw_h);

    // 1) prep: vectorized conversions + transpose + bias + ln1
    prep_w_kernel<<<B_CVT + B_F2T + 1 + NLN1, 256>>>(
        in_w, m_in_w, m_xp_w, m_out_w, f_w1,
        o_w, o_b, f_w2, f_b2, x, norm_g, norm_b);

    // 2) xp = xs @ in_w^T + in_b
    gemm_bf16_kernel<2, 2><<<dim3(3, 64, 1), 256>>>(p_xs_h, p_w_in, in_b, p_xp_h,
        LROWS, DM, DM, DM, DM, 0, 0, 0, 0, 0, 0, 1);

    // 3) xz[d] = gather_d(xp) @ m_in_w[d]^T
    gemm_bf16_kernel<4, 4><<<dim3(6, 32, 4), 256>>>(p_xp_h, p_w_inproj, nullptr, p_xz_h,
        LROWS, 2 * DI, DM, DM, 2 * DI,
        0, (long)2 * DI * DM, 0, (long)LROWS * 2 * DI, 0, 1, 1);

    // 4) causal depthwise conv + silu
    conv_silu_kernel<<<768, 256>>>(m_conv_w, m_conv_b);

    // 5) dbl[d] = xsm[d] @ m_xp_w[d]^T
    gemm_bf16_kernel<2, 2><<<dim3(1, 64, 4), 256>>>(p_xsm_h, p_w_xp, nullptr, p_dbl,
        LROWS, DBL_W, DI, DI, DBL_W,
        (long)LROWS * DI, (long)DBL_W * DI, 0, (long)LROWS * DBL_W, 0, 0, 0);

    // 6) selective scan (vectorized smem reads)
    scan_kernel<<<dim3(6, BATCH, NDIR), 256>>>(m_Alog, m_D, m_dt_w, m_dt_b);

    // 7) fused[:, d*DM:(d+1)*DM] = scatter_d(y[d] @ m_out_w[d]^T)
    gemm_bf16_kernel<4, 2><<<dim3(3, 32, 4), 256>>>(p_y_h, p_w_out, nullptr, p_fused_h,
        LROWS, DM, DI, DI, 4 * DM,
        (long)LROWS * DI, (long)DM * DI, 0, (long)DM, 0, 2, 1);

    // 8) Wc = o_w @ f_w2 (bf16 GEMM)
    gemm_bf16_kernel<2, 2><<<dim3(6, 3, 1), 256>>>(p_w_ow, p_w_f2T, nullptr, p_cw_h,
        DM, 2 * DM, DM, DM, 2 * DM, 0, 0, 0, 0, 0, 0, 1);

    // 9) hdn = gelu(fused @ f_w1^T + f_b1)
    gemm_bf16_kernel<4, 2><<<dim3(6, 32, 1), 256>>>(p_fused_h, p_w_f1, f_b1, p_hdn_h,
        LROWS, 2 * DM, 4 * DM, 4 * DM, 2 * DM, 0, 0, 0, 0, 2, 0, 1);

    // 10) h3 = hdn @ Wc^T + bc
    gemm_bf16_kernel<2, 2><<<dim3(3, 64, 1), 256>>>(p_hdn_h, p_cw_h, p_cb, p_h3,
        LROWS, DM, 2 * DM, 2 * DM, DM, 0, 0, 0, 0, 0, 0, 0);

    // 11) final layernorm + residual + transpose out
    ln2_kernel<<<dim3(64, 4), 256>>>(on_g, on_b, out);
}